// round 7
// baseline (speedup 1.0000x reference)
#include <cuda_runtime.h>
#include <cuda_bf16.h>
#include <math.h>
#include <stdint.h>

// ---------------- problem constants ----------------
#define BATCH 4
#define T_LEN 4096
#define DIM 1024
#define DI 2048            // d_inner
#define DSTATE 16
#define KCONV 4
#define NSCALES 3
#define ROWS_FULL (BATCH * T_LEN)          // 16384
#define LN_EPS 1e-5f

// ---------------- scratch (__device__ globals; no allocation allowed) ------
__device__ __align__(16) float g_xz[ROWS_FULL * 2 * DI];        // (x_in | gate)
__device__ __align__(16) float g_xc[ROWS_FULL * DI];            // conv+silu output
__device__ __align__(16) float g_bssm[ROWS_FULL * DSTATE];
__device__ __align__(16) float g_ys0[ROWS_FULL * DI];           // scale 0 ssm out
__device__ __align__(16) float g_ys1[(ROWS_FULL / 2) * DI];     // scale 1
__device__ __align__(16) float g_ys2[(ROWS_FULL / 4) * DI];     // scale 2
__device__ __align__(16) float g_fused[ROWS_FULL * DI];
__device__ __align__(16) float g_ctx[ROWS_FULL * DI];
__device__ __align__(16) float g_h[ROWS_FULL * (DI / 2)];
__device__ __align__(16) float g_mmin[ROWS_FULL * DI];
__device__ __align__(16) float g_preln[ROWS_FULL * DIM];
__device__ float g_sw[NSCALES];

// ---------------- helpers ----------------
__device__ __forceinline__ float sigmoidf(float x) { return 1.f / (1.f + expf(-x)); }
__device__ __forceinline__ float siluf(float x)    { return x / (1.f + expf(-x)); }
__device__ __forceinline__ float softplusf(float x){ return x > 20.f ? x : log1pf(expf(x)); }

__device__ __forceinline__ uint32_t f2tf32(float f) {
    uint32_t u;
    asm("cvt.rna.tf32.f32 %0, %1;" : "=r"(u) : "f"(f));
    return u;
}

__device__ __forceinline__ void mma_tf32(float* c, const uint32_t* a, uint32_t b0, uint32_t b1) {
    asm volatile(
        "mma.sync.aligned.m16n8k8.row.col.f32.tf32.tf32.f32 "
        "{%0,%1,%2,%3}, {%4,%5,%6,%7}, {%8,%9}, {%0,%1,%2,%3};\n"
        : "+f"(c[0]), "+f"(c[1]), "+f"(c[2]), "+f"(c[3])
        : "r"(a[0]), "r"(a[1]), "r"(a[2]), "r"(a[3]), "r"(b0), "r"(b1));
}

// ---------------- softmax over 3 scale weights ----------------
__global__ void softmax3_kernel(const float* __restrict__ sw) {
    float a = sw[0], b = sw[1], c = sw[2];
    float m = fmaxf(a, fmaxf(b, c));
    float ea = expf(a - m), eb = expf(b - m), ec = expf(c - m);
    float inv = 1.f / (ea + eb + ec);
    g_sw[0] = ea * inv; g_sw[1] = eb * inv; g_sw[2] = ec * inv;
}

// ---------------- TF32 tensor-core GEMM with fused epilogues (R4 structure) --
// C[M,N] = A[M,K] * B[K,N], row-major. M%128==0, N%128==0, K%32==0.
// Block tile 128x128, K-tile 32, 256 threads = 8 warps of 64(m)x32(n).
// EPI: 0=store, 1=silu, 2=sigmoid(acc)*e1[row*N+col]*silu(e2[row*4096+col]),
//      3=acc + e1[row*N+col]
template<int EPI>
__global__ __launch_bounds__(256, 2)
void tgemm_kernel(const float* __restrict__ A, const float* __restrict__ B,
                  float* __restrict__ C, int M, int N, int K,
                  const float* __restrict__ e1, const float* __restrict__ e2) {
    // A: [mi(8)][ki(4)][lane(33 pad)][slot(4)]  (fragment-ready, tf32 bits)
    __shared__ __align__(16) uint32_t Asm[8 * 4 * 33 * 4];
    // B: [ni(16)][ki2(2)][lane(32)][q(4)] with XOR swizzle on lane/q by ni
    __shared__ __align__(16) uint32_t Bsm[16 * 256];

    const int tid  = threadIdx.x;
    const int warp = tid >> 5;
    const int lane = tid & 31;
    const int wm = warp >> 2;          // 0..1 (64 rows each)
    const int wn = warp & 3;           // 0..3 (32 cols each)
    const int g  = lane >> 2;          // 0..7
    const int tg = lane & 3;           // 0..3

    const int m0 = blockIdx.y * 128;
    const int n0 = blockIdx.x * 128;

    float acc[4][4][4];
#pragma unroll
    for (int i = 0; i < 4; i++)
#pragma unroll
        for (int j = 0; j < 4; j++)
#pragma unroll
            for (int q = 0; q < 4; q++) acc[i][j][q] = 0.f;

    float4 a_pre[4], b_pre[4];

    // preload tile 0
#pragma unroll
    for (int it = 0; it < 4; it++) {
        int v = tid + it * 256;
        int r = v >> 3, c4 = (v & 7) * 4;
        a_pre[it] = *(const float4*)&A[(size_t)(m0 + r) * K + c4];
        int kk = v >> 5, n4 = (v & 31) * 4;
        b_pre[it] = *(const float4*)&B[(size_t)kk * N + n0 + n4];
    }

    for (int k0 = 0; k0 < K; k0 += 32) {
        // ---- scatter prefetched tile into fragment-ready smem ----
#pragma unroll
        for (int it = 0; it < 4; it++) {
            int v = tid + it * 256;
            {
                int r = v >> 3, c4 = (v & 7) * 4;
                float va[4] = {a_pre[it].x, a_pre[it].y, a_pre[it].z, a_pre[it].w};
#pragma unroll
                for (int j = 0; j < 4; j++) {
                    int c = c4 + j;
                    int mi = r >> 4, rr = r & 15, ki = c >> 3, cc = c & 7;
                    int ls = (rr & 7) * 4 + (cc & 3);
                    int slot = (cc >> 2) * 2 + (rr >> 3);
                    Asm[((mi * 4 + ki) * 33 + ls) * 4 + slot] = f2tf32(va[j]);
                }
            }
            {
                int kk = v >> 5, n4 = (v & 31) * 4;
                float vb[4] = {b_pre[it].x, b_pre[it].y, b_pre[it].z, b_pre[it].w};
#pragma unroll
                for (int j = 0; j < 4; j++) {
                    int nn = n4 + j;
                    int ni = nn >> 3, cc = nn & 7;
                    int ls = cc * 4 + (kk & 3);
                    int ki = kk >> 3;
                    int q = (ki & 1) * 2 + ((kk & 7) >> 2);
                    int lp = ls ^ (ni & 15);
                    int qp = q ^ (ni & 3);
                    Bsm[ni * 256 + (ki >> 1) * 128 + lp * 4 + qp] = f2tf32(vb[j]);
                }
            }
        }
        __syncthreads();

        // ---- prefetch next tile ----
        if (k0 + 32 < K) {
#pragma unroll
            for (int it = 0; it < 4; it++) {
                int v = tid + it * 256;
                int r = v >> 3, c4 = (v & 7) * 4;
                a_pre[it] = *(const float4*)&A[(size_t)(m0 + r) * K + (k0 + 32) + c4];
                int kk = v >> 5, n4 = (v & 31) * 4;
                b_pre[it] = *(const float4*)&B[(size_t)(k0 + 32 + kk) * N + n0 + n4];
            }
        }

        // ---- compute ----
#pragma unroll
        for (int ki2 = 0; ki2 < 2; ki2++) {
            uint32_t bq[4][4];
#pragma unroll
            for (int ni = 0; ni < 4; ni++) {
                int ni_g = wn * 4 + ni;
                int lp = lane ^ (ni_g & 15);
                *(uint4*)bq[ni] = *(const uint4*)&Bsm[ni_g * 256 + ki2 * 128 + lp * 4];
            }
#pragma unroll
            for (int h = 0; h < 2; h++) {
                int ki = ki2 * 2 + h;
                uint32_t af[4][4];
#pragma unroll
                for (int mi = 0; mi < 4; mi++) {
                    int mi_g = wm * 4 + mi;
                    *(uint4*)af[mi] = *(const uint4*)&Asm[((mi_g * 4 + ki) * 33 + lane) * 4];
                }
#pragma unroll
                for (int mi = 0; mi < 4; mi++)
#pragma unroll
                    for (int ni = 0; ni < 4; ni++) {
                        const int p = ni & 3;   // (wn*4+ni)&3 == ni&3, compile-time
                        uint32_t b0 = bq[ni][(h * 2 + 0) ^ p];
                        uint32_t b1 = bq[ni][(h * 2 + 1) ^ p];
                        mma_tf32(acc[mi][ni], af[mi], b0, b1);
                    }
            }
        }
        __syncthreads();
    }

    // ---- epilogue ----
#pragma unroll
    for (int mi = 0; mi < 4; mi++) {
#pragma unroll
        for (int ni = 0; ni < 4; ni++) {
            int r0 = m0 + wm * 64 + mi * 16 + g;
            int cb = n0 + wn * 32 + ni * 8 + tg * 2;
#pragma unroll
            for (int half = 0; half < 2; half++) {
                int row = r0 + half * 8;
                float v0 = acc[mi][ni][half * 2 + 0];
                float v1 = acc[mi][ni][half * 2 + 1];
                size_t idx = (size_t)row * N + cb;
                float o0, o1;
                if (EPI == 0) {
                    o0 = v0; o1 = v1;
                } else if (EPI == 1) {
                    o0 = siluf(v0); o1 = siluf(v1);
                } else if (EPI == 2) {
                    float g0 = e2[(size_t)row * (2 * DI) + cb];
                    float g1 = e2[(size_t)row * (2 * DI) + cb + 1];
                    o0 = e1[idx] * sigmoidf(v0) * siluf(g0);
                    o1 = e1[idx + 1] * sigmoidf(v1) * siluf(g1);
                } else {
                    o0 = v0 + e1[idx];
                    o1 = v1 + e1[idx + 1];
                }
                *(float2*)&C[idx] = make_float2(o0, o1);
            }
        }
    }
}

// ---------------- causal depthwise conv (K=4) + silu, fused downsample ------
__global__ void conv_silu_kernel(const float* __restrict__ xz,
                                 const float* __restrict__ w, const float* __restrict__ b,
                                 float* __restrict__ xc, int Ts, int stride) {
    int idx = blockIdx.x * blockDim.x + threadIdx.x;
    int total = BATCH * Ts * DI;
    if (idx >= total) return;
    int c = idx & (DI - 1);
    int rt = idx / DI;
    int t = rt % Ts;
    int bb = rt / Ts;
    float inv = 1.f / (float)stride;
    float acc = b[c];
#pragma unroll
    for (int k = 0; k < KCONV; k++) {
        int tt = t - (KCONV - 1) + k;
        if (tt >= 0) {
            float v = 0.f;
            for (int r = 0; r < stride; r++)
                v += xz[(size_t)(bb * T_LEN + tt * stride + r) * (2 * DI) + c];
            acc = fmaf(w[c * KCONV + k], v * inv, acc);
        }
    }
    xc[idx] = siluf(acc);
}

// ---------------- B_ssm = xc @ xproj[:, :16] ----------------
__global__ __launch_bounds__(256)
void bssm_kernel(const float* __restrict__ xc, const float* __restrict__ xproj,
                 float* __restrict__ bssm) {
    __shared__ float xs[16][64];
    __shared__ float ws[64][16];
    int row0 = blockIdx.x * 16;
    int r = threadIdx.x >> 4;
    int j = threadIdx.x & 15;
    float acc = 0.f;
    for (int k0 = 0; k0 < DI; k0 += 64) {
        int v = threadIdx.x;
        int lr = v >> 4;
        int lc4 = (v & 15) * 4;
        *(float4*)&xs[lr][lc4] = *(const float4*)&xc[(size_t)(row0 + lr) * DI + k0 + lc4];
#pragma unroll
        for (int it = 0; it < 4; it++) {
            int kk = it * 16 + (threadIdx.x >> 4);
            int jj = threadIdx.x & 15;
            ws[kk][jj] = xproj[(size_t)(k0 + kk) * (2 * DSTATE) + jj];
        }
        __syncthreads();
#pragma unroll
        for (int kk = 0; kk < 64; kk++) acc = fmaf(xs[r][kk], ws[kk][j], acc);
        __syncthreads();
    }
    bssm[(size_t)(row0 + r) * DSTATE + j] = acc;
}

// ---------------- SSM pointwise (fused downsample for the D*x term) --------
__global__ __launch_bounds__(256)
void ssm_pw_kernel(const float* __restrict__ xc, const float* __restrict__ bssm,
                   const float* __restrict__ dtw, const float* __restrict__ dtb,
                   const float* __restrict__ D, const float* __restrict__ xz,
                   int Ts, int stride, float* __restrict__ ys) {
    int row = blockIdx.x;
    int t = row % Ts;
    int bb = row / Ts;
    float inv = 1.f / (float)stride;
    __shared__ float bs[DSTATE];
    if (threadIdx.x < DSTATE) bs[threadIdx.x] = bssm[(size_t)row * DSTATE + threadIdx.x];
    __syncthreads();
    for (int c = threadIdx.x; c < DI; c += 256) {
        float dt = dtb[c];
#pragma unroll
        for (int k = 0; k < DSTATE; k++) dt = fmaf(bs[k], dtw[k * DI + c], dt);
        float sg = sigmoidf(softplusf(dt));
        float xv = 0.f;
        for (int r = 0; r < stride; r++)
            xv += xz[(size_t)(bb * T_LEN + t * stride + r) * (2 * DI) + c];
        xv *= inv;
        ys[(size_t)row * DI + c] = xc[(size_t)row * DI + c] * sg + D[c] * xv;
    }
}

// ---------------- merged upsample + fuse (all 3 scales in one pass) ----------
__global__ void ups_fuse_kernel(const float* __restrict__ ys0,
                                const float* __restrict__ ys1,
                                const float* __restrict__ ys2,
                                float* __restrict__ fused, float* __restrict__ ctx) {
    int idx = blockIdx.x * blockDim.x + threadIdx.x;
    const int total4 = ROWS_FULL * (DI / 4);
    if (idx >= total4) return;
    int c4 = (idx & (DI / 4 - 1)) * 4;
    int rt = idx / (DI / 4);
    int t = rt % T_LEN;
    int bb = rt / T_LEN;

    float4 v0 = *(const float4*)&ys0[(size_t)(bb * T_LEN + t) * DI + c4];

    float4 v1, v2;
    {   // scale 1: Ts = 2048
        const int Ts = T_LEN / 2;
        float coord = (t + 0.5f) * 0.5f - 0.5f;
        coord = fminf(fmaxf(coord, 0.f), (float)(Ts - 1));
        int lo = (int)floorf(coord);
        int hi = min(lo + 1, Ts - 1);
        float wf = coord - (float)lo;
        float4 a = *(const float4*)&ys1[(size_t)(bb * Ts + lo) * DI + c4];
        float4 b = *(const float4*)&ys1[(size_t)(bb * Ts + hi) * DI + c4];
        v1.x = a.x + (b.x - a.x) * wf; v1.y = a.y + (b.y - a.y) * wf;
        v1.z = a.z + (b.z - a.z) * wf; v1.w = a.w + (b.w - a.w) * wf;
    }
    {   // scale 2: Ts = 1024
        const int Ts = T_LEN / 4;
        float coord = (t + 0.5f) * 0.25f - 0.5f;
        coord = fminf(fmaxf(coord, 0.f), (float)(Ts - 1));
        int lo = (int)floorf(coord);
        int hi = min(lo + 1, Ts - 1);
        float wf = coord - (float)lo;
        float4 a = *(const float4*)&ys2[(size_t)(bb * Ts + lo) * DI + c4];
        float4 b = *(const float4*)&ys2[(size_t)(bb * Ts + hi) * DI + c4];
        v2.x = a.x + (b.x - a.x) * wf; v2.y = a.y + (b.y - a.y) * wf;
        v2.z = a.z + (b.z - a.z) * wf; v2.w = a.w + (b.w - a.w) * wf;
    }

    float w0 = g_sw[0], w1 = g_sw[1], w2 = g_sw[2];
    float4 f, cx;
    f.x = w0 * v0.x + w1 * v1.x + w2 * v2.x;
    f.y = w0 * v0.y + w1 * v1.y + w2 * v2.y;
    f.z = w0 * v0.z + w1 * v1.z + w2 * v2.z;
    f.w = w0 * v0.w + w1 * v1.w + w2 * v2.w;
    const float third = 1.f / 3.f;
    cx.x = (v0.x + v1.x + v2.x) * third;
    cx.y = (v0.y + v1.y + v2.y) * third;
    cx.z = (v0.z + v1.z + v2.z) * third;
    cx.w = (v0.w + v1.w + v2.w) * third;

    size_t o = (size_t)rt * DI + c4;
    *(float4*)&fused[o] = f;
    *(float4*)&ctx[o] = cx;
}

// ---------------- LayerNorm over last dim (1024) ----------------
__global__ __launch_bounds__(256)
void ln_kernel(const float* __restrict__ y, const float* __restrict__ g,
               const float* __restrict__ b, float* __restrict__ out) {
    int row = blockIdx.x;
    const float* yr = y + (size_t)row * DIM;
    float s = 0.f, s2 = 0.f;
    for (int c = threadIdx.x; c < DIM; c += 256) {
        float v = yr[c];
        s += v; s2 += v * v;
    }
#pragma unroll
    for (int o = 16; o > 0; o >>= 1) {
        s  += __shfl_down_sync(0xffffffffu, s, o);
        s2 += __shfl_down_sync(0xffffffffu, s2, o);
    }
    __shared__ float shs[8], shs2[8];
    __shared__ float smu, srstd;
    int wid = threadIdx.x >> 5, lane = threadIdx.x & 31;
    if (lane == 0) { shs[wid] = s; shs2[wid] = s2; }
    __syncthreads();
    if (wid == 0) {
        s  = lane < 8 ? shs[lane]  : 0.f;
        s2 = lane < 8 ? shs2[lane] : 0.f;
#pragma unroll
        for (int o = 4; o > 0; o >>= 1) {
            s  += __shfl_down_sync(0xffffffffu, s, o);
            s2 += __shfl_down_sync(0xffffffffu, s2, o);
        }
        if (lane == 0) {
            float mu = s / DIM;
            float var = s2 / DIM - mu * mu;
            smu = mu;
            srstd = rsqrtf(var + LN_EPS);
        }
    }
    __syncthreads();
    float mu = smu, rstd = srstd;
    for (int c = threadIdx.x; c < DIM; c += 256) {
        out[(size_t)row * DIM + c] = (yr[c] - mu) * rstd * g[c] + b[c];
    }
}

// ---------------- launch ----------------
extern "C" void kernel_launch(void* const* d_in, const int* in_sizes, int n_in,
                              void* d_out, int out_size) {
    const float* x        = (const float*)d_in[0];
    const float* in_proj  = (const float*)d_in[1];
    const float* conv_w   = (const float*)d_in[2];
    const float* conv_b   = (const float*)d_in[3];
    const float* xproj_w  = (const float*)d_in[4];
    const float* dtproj_w = (const float*)d_in[5];
    const float* dtproj_b = (const float*)d_in[6];
    const float* D_param  = (const float*)d_in[7];
    const float* scale_w  = (const float*)d_in[8];
    const float* cg_w1    = (const float*)d_in[9];
    const float* cg_w2    = (const float*)d_in[10];
    const float* out_proj = (const float*)d_in[11];
    const float* ln_g     = (const float*)d_in[12];
    const float* ln_b     = (const float*)d_in[13];
    float* out = (float*)d_out;

    float *p_xz, *p_xc, *p_bssm, *p_ys0, *p_ys1, *p_ys2,
          *p_fused, *p_ctx, *p_h, *p_mmin, *p_preln;
    cudaGetSymbolAddress((void**)&p_xz, g_xz);
    cudaGetSymbolAddress((void**)&p_xc, g_xc);
    cudaGetSymbolAddress((void**)&p_bssm, g_bssm);
    cudaGetSymbolAddress((void**)&p_ys0, g_ys0);
    cudaGetSymbolAddress((void**)&p_ys1, g_ys1);
    cudaGetSymbolAddress((void**)&p_ys2, g_ys2);
    cudaGetSymbolAddress((void**)&p_fused, g_fused);
    cudaGetSymbolAddress((void**)&p_ctx, g_ctx);
    cudaGetSymbolAddress((void**)&p_h, g_h);
    cudaGetSymbolAddress((void**)&p_mmin, g_mmin);
    cudaGetSymbolAddress((void**)&p_preln, g_preln);

    softmax3_kernel<<<1, 1>>>(scale_w);

    // 1) xz = x @ in_proj_w   (16384 x 4096, K=1024)
    {
        dim3 grid(2 * DI / 128, ROWS_FULL / 128);
        tgemm_kernel<0><<<grid, 256>>>(x, in_proj, p_xz, ROWS_FULL, 2 * DI, DIM,
                                       nullptr, nullptr);
    }

    // 2) per-scale SSM path (downsample fused into conv / ssm_pw)
    float* ys_bufs[NSCALES] = {p_ys0, p_ys1, p_ys2};
    for (int s = 0; s < NSCALES; s++) {
        int stride = 1 << s;
        int Ts = T_LEN / stride;
        int rows = BATCH * Ts;
        int total = rows * DI;
        conv_silu_kernel<<<(total + 255) / 256, 256>>>(p_xz,
                                                       conv_w + (size_t)s * DI * KCONV,
                                                       conv_b + (size_t)s * DI,
                                                       p_xc, Ts, stride);
        bssm_kernel<<<rows / 16, 256>>>(p_xc, xproj_w + (size_t)s * DI * 2 * DSTATE, p_bssm);
        ssm_pw_kernel<<<rows, 256>>>(p_xc, p_bssm,
                                     dtproj_w + (size_t)s * DSTATE * DI,
                                     dtproj_b + (size_t)s * DI,
                                     D_param + (size_t)s * DI,
                                     p_xz, Ts, stride, ys_bufs[s]);
    }

    // 2b) merged upsample + fuse
    {
        int total4 = ROWS_FULL * (DI / 4);
        ups_fuse_kernel<<<(total4 + 255) / 256, 256>>>(p_ys0, p_ys1, p_ys2, p_fused, p_ctx);
    }

    // 3) h = silu(ctx @ cg_w1)   (16384 x 1024, K=2048)
    {
        dim3 grid((DI / 2) / 128, ROWS_FULL / 128);
        tgemm_kernel<1><<<grid, 256>>>(p_ctx, cg_w1, p_h, ROWS_FULL, DI / 2, DI,
                                       nullptr, nullptr);
    }
    // 4) mm_in = fused * sigmoid(h @ cg_w2) * silu(gate)  (16384 x 2048, K=1024)
    {
        dim3 grid(DI / 128, ROWS_FULL / 128);
        tgemm_kernel<2><<<grid, 256>>>(p_h, cg_w2, p_mmin, ROWS_FULL, DI, DI / 2,
                                       p_fused, p_xz + DI);
    }
    // 5) preln = mm_in @ out_proj + x   (16384 x 1024, K=2048)
    {
        dim3 grid(DIM / 128, ROWS_FULL / 128);
        tgemm_kernel<3><<<grid, 256>>>(p_mmin, out_proj, p_preln, ROWS_FULL, DIM, DI,
                                       x, nullptr);
    }
    // 6) LayerNorm -> out
    ln_kernel<<<ROWS_FULL, 256>>>(p_preln, ln_g, ln_b, out);
}

// round 8
// speedup vs baseline: 1.0714x; 1.0714x over previous
#include <cuda_runtime.h>
#include <cuda_bf16.h>
#include <math.h>
#include <stdint.h>

// ---------------- problem constants ----------------
#define BATCH 4
#define T_LEN 4096
#define DIM 1024
#define DI 2048            // d_inner
#define DSTATE 16
#define KCONV 4
#define NSCALES 3
#define ROWS_FULL (BATCH * T_LEN)          // 16384
#define LN_EPS 1e-5f

// ---------------- scratch (__device__ globals; no allocation allowed) ------
__device__ __align__(16) float g_xz[ROWS_FULL * 2 * DI];        // (x_in | gate)
__device__ __align__(16) float g_xc[ROWS_FULL * DI];            // conv+silu output
__device__ __align__(16) float g_bssm[ROWS_FULL * DSTATE];
__device__ __align__(16) float g_ys0[ROWS_FULL * DI];           // scale 0 ssm out
__device__ __align__(16) float g_ys1[(ROWS_FULL / 2) * DI];     // scale 1
__device__ __align__(16) float g_ys2[(ROWS_FULL / 4) * DI];     // scale 2
__device__ __align__(16) float g_fused[ROWS_FULL * DI];
__device__ __align__(16) float g_ctx[ROWS_FULL * DI];
__device__ __align__(16) float g_h[ROWS_FULL * (DI / 2)];
__device__ __align__(16) float g_mmin[ROWS_FULL * DI];
__device__ __align__(16) float g_preln[ROWS_FULL * DIM];
__device__ float g_sw[NSCALES];

// ---------------- helpers ----------------
__device__ __forceinline__ float sigmoidf(float x) { return 1.f / (1.f + expf(-x)); }
__device__ __forceinline__ float siluf(float x)    { return x / (1.f + expf(-x)); }
__device__ __forceinline__ float softplusf(float x){ return x > 20.f ? x : log1pf(expf(x)); }

__device__ __forceinline__ uint32_t f2tf32(float f) {
    uint32_t u;
    asm("cvt.rna.tf32.f32 %0, %1;" : "=r"(u) : "f"(f));
    return u;
}

__device__ __forceinline__ void mma_tf32(float* c, const uint32_t* a, uint32_t b0, uint32_t b1) {
    asm volatile(
        "mma.sync.aligned.m16n8k8.row.col.f32.tf32.tf32.f32 "
        "{%0,%1,%2,%3}, {%4,%5,%6,%7}, {%8,%9}, {%0,%1,%2,%3};\n"
        : "+f"(c[0]), "+f"(c[1]), "+f"(c[2]), "+f"(c[3])
        : "r"(a[0]), "r"(a[1]), "r"(a[2]), "r"(a[3]), "r"(b0), "r"(b1));
}

// ---------------- softmax over 3 scale weights ----------------
__global__ void softmax3_kernel(const float* __restrict__ sw) {
    float a = sw[0], b = sw[1], c = sw[2];
    float m = fmaxf(a, fmaxf(b, c));
    float ea = expf(a - m), eb = expf(b - m), ec = expf(c - m);
    float inv = 1.f / (ea + eb + ec);
    g_sw[0] = ea * inv; g_sw[1] = eb * inv; g_sw[2] = ec * inv;
}

// ---------------- TF32 tensor-core GEMM with fused epilogues (R4 verbatim) --
// C[M,N] = A[M,K] * B[K,N], row-major. M%128==0, N%128==0, K%32==0.
// Block tile 128x128, K-tile 32, 256 threads = 8 warps of 64(m)x32(n).
// EPI: 0=store, 1=silu, 2=sigmoid(acc)*e1[row*N+col]*silu(e2[row*4096+col]),
//      3=acc + e1[row*N+col]
template<int EPI>
__global__ __launch_bounds__(256)
void tgemm_kernel(const float* __restrict__ A, const float* __restrict__ B,
                  float* __restrict__ C, int M, int N, int K,
                  const float* __restrict__ e1, const float* __restrict__ e2) {
    // A: [mi(8)][ki(4)][lane(33 pad)][slot(4)]  (fragment-ready, tf32 bits)
    __shared__ __align__(16) uint32_t Asm[8 * 4 * 33 * 4];
    // B: [ni(16)][ki2(2)][lane(32)][q(4)] with XOR swizzle on lane/q by ni
    __shared__ __align__(16) uint32_t Bsm[16 * 256];

    const int tid  = threadIdx.x;
    const int warp = tid >> 5;
    const int lane = tid & 31;
    const int wm = warp >> 2;          // 0..1 (64 rows each)
    const int wn = warp & 3;           // 0..3 (32 cols each)
    const int g  = lane >> 2;          // 0..7
    const int tg = lane & 3;           // 0..3

    const int m0 = blockIdx.y * 128;
    const int n0 = blockIdx.x * 128;

    float acc[4][4][4];
#pragma unroll
    for (int i = 0; i < 4; i++)
#pragma unroll
        for (int j = 0; j < 4; j++)
#pragma unroll
            for (int q = 0; q < 4; q++) acc[i][j][q] = 0.f;

    float4 a_pre[4], b_pre[4];

    // preload tile 0
#pragma unroll
    for (int it = 0; it < 4; it++) {
        int v = tid + it * 256;
        int r = v >> 3, c4 = (v & 7) * 4;
        a_pre[it] = *(const float4*)&A[(size_t)(m0 + r) * K + c4];
        int kk = v >> 5, n4 = (v & 31) * 4;
        b_pre[it] = *(const float4*)&B[(size_t)kk * N + n0 + n4];
    }

    for (int k0 = 0; k0 < K; k0 += 32) {
        // ---- scatter prefetched tile into fragment-ready smem ----
#pragma unroll
        for (int it = 0; it < 4; it++) {
            int v = tid + it * 256;
            {
                int r = v >> 3, c4 = (v & 7) * 4;
                float va[4] = {a_pre[it].x, a_pre[it].y, a_pre[it].z, a_pre[it].w};
#pragma unroll
                for (int j = 0; j < 4; j++) {
                    int c = c4 + j;
                    int mi = r >> 4, rr = r & 15, ki = c >> 3, cc = c & 7;
                    int ls = (rr & 7) * 4 + (cc & 3);
                    int slot = (cc >> 2) * 2 + (rr >> 3);
                    Asm[((mi * 4 + ki) * 33 + ls) * 4 + slot] = f2tf32(va[j]);
                }
            }
            {
                int kk = v >> 5, n4 = (v & 31) * 4;
                float vb[4] = {b_pre[it].x, b_pre[it].y, b_pre[it].z, b_pre[it].w};
#pragma unroll
                for (int j = 0; j < 4; j++) {
                    int nn = n4 + j;
                    int ni = nn >> 3, cc = nn & 7;
                    int ls = cc * 4 + (kk & 3);
                    int ki = kk >> 3;
                    int q = (ki & 1) * 2 + ((kk & 7) >> 2);
                    int lp = ls ^ (ni & 15);
                    int qp = q ^ (ni & 3);
                    Bsm[ni * 256 + (ki >> 1) * 128 + lp * 4 + qp] = f2tf32(vb[j]);
                }
            }
        }
        __syncthreads();

        // ---- prefetch next tile ----
        if (k0 + 32 < K) {
#pragma unroll
            for (int it = 0; it < 4; it++) {
                int v = tid + it * 256;
                int r = v >> 3, c4 = (v & 7) * 4;
                a_pre[it] = *(const float4*)&A[(size_t)(m0 + r) * K + (k0 + 32) + c4];
                int kk = v >> 5, n4 = (v & 31) * 4;
                b_pre[it] = *(const float4*)&B[(size_t)(k0 + 32 + kk) * N + n0 + n4];
            }
        }

        // ---- compute ----
#pragma unroll
        for (int ki2 = 0; ki2 < 2; ki2++) {
            uint32_t bq[4][4];
#pragma unroll
            for (int ni = 0; ni < 4; ni++) {
                int ni_g = wn * 4 + ni;
                int lp = lane ^ (ni_g & 15);
                *(uint4*)bq[ni] = *(const uint4*)&Bsm[ni_g * 256 + ki2 * 128 + lp * 4];
            }
#pragma unroll
            for (int h = 0; h < 2; h++) {
                int ki = ki2 * 2 + h;
                uint32_t af[4][4];
#pragma unroll
                for (int mi = 0; mi < 4; mi++) {
                    int mi_g = wm * 4 + mi;
                    *(uint4*)af[mi] = *(const uint4*)&Asm[((mi_g * 4 + ki) * 33 + lane) * 4];
                }
#pragma unroll
                for (int mi = 0; mi < 4; mi++)
#pragma unroll
                    for (int ni = 0; ni < 4; ni++) {
                        const int p = ni & 3;   // (wn*4+ni)&3 == ni&3, compile-time
                        uint32_t b0 = bq[ni][(h * 2 + 0) ^ p];
                        uint32_t b1 = bq[ni][(h * 2 + 1) ^ p];
                        mma_tf32(acc[mi][ni], af[mi], b0, b1);
                    }
            }
        }
        __syncthreads();
    }

    // ---- epilogue ----
#pragma unroll
    for (int mi = 0; mi < 4; mi++) {
#pragma unroll
        for (int ni = 0; ni < 4; ni++) {
            int r0 = m0 + wm * 64 + mi * 16 + g;
            int cb = n0 + wn * 32 + ni * 8 + tg * 2;
#pragma unroll
            for (int half = 0; half < 2; half++) {
                int row = r0 + half * 8;
                float v0 = acc[mi][ni][half * 2 + 0];
                float v1 = acc[mi][ni][half * 2 + 1];
                size_t idx = (size_t)row * N + cb;
                float o0, o1;
                if (EPI == 0) {
                    o0 = v0; o1 = v1;
                } else if (EPI == 1) {
                    o0 = siluf(v0); o1 = siluf(v1);
                } else if (EPI == 2) {
                    float g0 = e2[(size_t)row * (2 * DI) + cb];
                    float g1 = e2[(size_t)row * (2 * DI) + cb + 1];
                    o0 = e1[idx] * sigmoidf(v0) * siluf(g0);
                    o1 = e1[idx + 1] * sigmoidf(v1) * siluf(g1);
                } else {
                    o0 = v0 + e1[idx];
                    o1 = v1 + e1[idx + 1];
                }
                *(float2*)&C[idx] = make_float2(o0, o1);
            }
        }
    }
}

// ---------------- causal depthwise conv (K=4) + silu, fused downsample ------
__global__ void conv_silu_kernel(const float* __restrict__ xz,
                                 const float* __restrict__ w, const float* __restrict__ b,
                                 float* __restrict__ xc, int Ts, int stride) {
    int idx = blockIdx.x * blockDim.x + threadIdx.x;
    int total = BATCH * Ts * DI;
    if (idx >= total) return;
    int c = idx & (DI - 1);
    int rt = idx / DI;
    int t = rt % Ts;
    int bb = rt / Ts;
    float inv = 1.f / (float)stride;
    float acc = b[c];
#pragma unroll
    for (int k = 0; k < KCONV; k++) {
        int tt = t - (KCONV - 1) + k;
        if (tt >= 0) {
            float v = 0.f;
            for (int r = 0; r < stride; r++)
                v += xz[(size_t)(bb * T_LEN + tt * stride + r) * (2 * DI) + c];
            acc = fmaf(w[c * KCONV + k], v * inv, acc);
        }
    }
    xc[idx] = siluf(acc);
}

// ---------------- B_ssm = xc @ xproj[:, :16]  (low-LDS version) -------------
// Block = 64 rows x 16 cols; thread (r, jq) computes cols jq*4..jq*4+3.
// Inner iter: 1 LDS.32 (4-thread broadcast) + 1 LDS.128 + 4 FMA.
__global__ __launch_bounds__(256)
void bssm_kernel(const float* __restrict__ xc, const float* __restrict__ xproj,
                 float* __restrict__ bssm) {
    __shared__ float xs[64 * 68];                 // row stride 68: conflict-free
    __shared__ __align__(16) float ws[64 * 16];
    const int tid = threadIdx.x;
    const int row0 = blockIdx.x * 64;
    const int r  = tid >> 2;
    const int jq = tid & 3;
    float acc[4] = {0.f, 0.f, 0.f, 0.f};

    for (int k0 = 0; k0 < DI; k0 += 64) {
#pragma unroll
        for (int i = 0; i < 4; i++) {
            int v = tid + i * 256;
            int lr = v >> 4, c4 = (v & 15) * 4;
            *(float4*)&xs[lr * 68 + c4] = *(const float4*)&xc[(size_t)(row0 + lr) * DI + k0 + c4];
        }
#pragma unroll
        for (int i = 0; i < 4; i++) {
            int v = tid + i * 256;
            int kk = v >> 4, j = v & 15;
            ws[kk * 16 + j] = xproj[(size_t)(k0 + kk) * (2 * DSTATE) + j];
        }
        __syncthreads();
#pragma unroll 16
        for (int kk = 0; kk < 64; kk++) {
            float xv = xs[r * 68 + kk];
            float4 w4 = *(const float4*)&ws[kk * 16 + jq * 4];
            acc[0] = fmaf(xv, w4.x, acc[0]);
            acc[1] = fmaf(xv, w4.y, acc[1]);
            acc[2] = fmaf(xv, w4.z, acc[2]);
            acc[3] = fmaf(xv, w4.w, acc[3]);
        }
        __syncthreads();
    }
    *(float4*)&bssm[(size_t)(row0 + r) * DSTATE + jq * 4] = *(float4*)acc;
}

// ---------------- SSM pointwise (fused downsample for the D*x term) --------
__global__ __launch_bounds__(256)
void ssm_pw_kernel(const float* __restrict__ xc, const float* __restrict__ bssm,
                   const float* __restrict__ dtw, const float* __restrict__ dtb,
                   const float* __restrict__ D, const float* __restrict__ xz,
                   int Ts, int stride, float* __restrict__ ys) {
    int row = blockIdx.x;
    int t = row % Ts;
    int bb = row / Ts;
    float inv = 1.f / (float)stride;
    __shared__ float bs[DSTATE];
    if (threadIdx.x < DSTATE) bs[threadIdx.x] = bssm[(size_t)row * DSTATE + threadIdx.x];
    __syncthreads();
    for (int c = threadIdx.x; c < DI; c += 256) {
        float dt = dtb[c];
#pragma unroll
        for (int k = 0; k < DSTATE; k++) dt = fmaf(bs[k], dtw[k * DI + c], dt);
        float sg = sigmoidf(softplusf(dt));
        float xv = 0.f;
        for (int r = 0; r < stride; r++)
            xv += xz[(size_t)(bb * T_LEN + t * stride + r) * (2 * DI) + c];
        xv *= inv;
        ys[(size_t)row * DI + c] = xc[(size_t)row * DI + c] * sg + D[c] * xv;
    }
}

// ---------------- merged upsample + fuse (all 3 scales in one pass) ----------
__global__ void ups_fuse_kernel(const float* __restrict__ ys0,
                                const float* __restrict__ ys1,
                                const float* __restrict__ ys2,
                                float* __restrict__ fused, float* __restrict__ ctx) {
    int idx = blockIdx.x * blockDim.x + threadIdx.x;
    const int total4 = ROWS_FULL * (DI / 4);
    if (idx >= total4) return;
    int c4 = (idx & (DI / 4 - 1)) * 4;
    int rt = idx / (DI / 4);
    int t = rt % T_LEN;
    int bb = rt / T_LEN;

    float4 v0 = *(const float4*)&ys0[(size_t)(bb * T_LEN + t) * DI + c4];

    float4 v1, v2;
    {   // scale 1: Ts = 2048
        const int Ts = T_LEN / 2;
        float coord = (t + 0.5f) * 0.5f - 0.5f;
        coord = fminf(fmaxf(coord, 0.f), (float)(Ts - 1));
        int lo = (int)floorf(coord);
        int hi = min(lo + 1, Ts - 1);
        float wf = coord - (float)lo;
        float4 a = *(const float4*)&ys1[(size_t)(bb * Ts + lo) * DI + c4];
        float4 b = *(const float4*)&ys1[(size_t)(bb * Ts + hi) * DI + c4];
        v1.x = a.x + (b.x - a.x) * wf; v1.y = a.y + (b.y - a.y) * wf;
        v1.z = a.z + (b.z - a.z) * wf; v1.w = a.w + (b.w - a.w) * wf;
    }
    {   // scale 2: Ts = 1024
        const int Ts = T_LEN / 4;
        float coord = (t + 0.5f) * 0.25f - 0.5f;
        coord = fminf(fmaxf(coord, 0.f), (float)(Ts - 1));
        int lo = (int)floorf(coord);
        int hi = min(lo + 1, Ts - 1);
        float wf = coord - (float)lo;
        float4 a = *(const float4*)&ys2[(size_t)(bb * Ts + lo) * DI + c4];
        float4 b = *(const float4*)&ys2[(size_t)(bb * Ts + hi) * DI + c4];
        v2.x = a.x + (b.x - a.x) * wf; v2.y = a.y + (b.y - a.y) * wf;
        v2.z = a.z + (b.z - a.z) * wf; v2.w = a.w + (b.w - a.w) * wf;
    }

    float w0 = g_sw[0], w1 = g_sw[1], w2 = g_sw[2];
    float4 f, cx;
    f.x = w0 * v0.x + w1 * v1.x + w2 * v2.x;
    f.y = w0 * v0.y + w1 * v1.y + w2 * v2.y;
    f.z = w0 * v0.z + w1 * v1.z + w2 * v2.z;
    f.w = w0 * v0.w + w1 * v1.w + w2 * v2.w;
    const float third = 1.f / 3.f;
    cx.x = (v0.x + v1.x + v2.x) * third;
    cx.y = (v0.y + v1.y + v2.y) * third;
    cx.z = (v0.z + v1.z + v2.z) * third;
    cx.w = (v0.w + v1.w + v2.w) * third;

    size_t o = (size_t)rt * DI + c4;
    *(float4*)&fused[o] = f;
    *(float4*)&ctx[o] = cx;
}

// ---------------- LayerNorm over last dim (1024) ----------------
__global__ __launch_bounds__(256)
void ln_kernel(const float* __restrict__ y, const float* __restrict__ g,
               const float* __restrict__ b, float* __restrict__ out) {
    int row = blockIdx.x;
    const float* yr = y + (size_t)row * DIM;
    float s = 0.f, s2 = 0.f;
    for (int c = threadIdx.x; c < DIM; c += 256) {
        float v = yr[c];
        s += v; s2 += v * v;
    }
#pragma unroll
    for (int o = 16; o > 0; o >>= 1) {
        s  += __shfl_down_sync(0xffffffffu, s, o);
        s2 += __shfl_down_sync(0xffffffffu, s2, o);
    }
    __shared__ float shs[8], shs2[8];
    __shared__ float smu, srstd;
    int wid = threadIdx.x >> 5, lane = threadIdx.x & 31;
    if (lane == 0) { shs[wid] = s; shs2[wid] = s2; }
    __syncthreads();
    if (wid == 0) {
        s  = lane < 8 ? shs[lane]  : 0.f;
        s2 = lane < 8 ? shs2[lane] : 0.f;
#pragma unroll
        for (int o = 4; o > 0; o >>= 1) {
            s  += __shfl_down_sync(0xffffffffu, s, o);
            s2 += __shfl_down_sync(0xffffffffu, s2, o);
        }
        if (lane == 0) {
            float mu = s / DIM;
            float var = s2 / DIM - mu * mu;
            smu = mu;
            srstd = rsqrtf(var + LN_EPS);
        }
    }
    __syncthreads();
    float mu = smu, rstd = srstd;
    for (int c = threadIdx.x; c < DIM; c += 256) {
        out[(size_t)row * DIM + c] = (yr[c] - mu) * rstd * g[c] + b[c];
    }
}

// ---------------- launch ----------------
extern "C" void kernel_launch(void* const* d_in, const int* in_sizes, int n_in,
                              void* d_out, int out_size) {
    const float* x        = (const float*)d_in[0];
    const float* in_proj  = (const float*)d_in[1];
    const float* conv_w   = (const float*)d_in[2];
    const float* conv_b   = (const float*)d_in[3];
    const float* xproj_w  = (const float*)d_in[4];
    const float* dtproj_w = (const float*)d_in[5];
    const float* dtproj_b = (const float*)d_in[6];
    const float* D_param  = (const float*)d_in[7];
    const float* scale_w  = (const float*)d_in[8];
    const float* cg_w1    = (const float*)d_in[9];
    const float* cg_w2    = (const float*)d_in[10];
    const float* out_proj = (const float*)d_in[11];
    const float* ln_g     = (const float*)d_in[12];
    const float* ln_b     = (const float*)d_in[13];
    float* out = (float*)d_out;

    float *p_xz, *p_xc, *p_bssm, *p_ys0, *p_ys1, *p_ys2,
          *p_fused, *p_ctx, *p_h, *p_mmin, *p_preln;
    cudaGetSymbolAddress((void**)&p_xz, g_xz);
    cudaGetSymbolAddress((void**)&p_xc, g_xc);
    cudaGetSymbolAddress((void**)&p_bssm, g_bssm);
    cudaGetSymbolAddress((void**)&p_ys0, g_ys0);
    cudaGetSymbolAddress((void**)&p_ys1, g_ys1);
    cudaGetSymbolAddress((void**)&p_ys2, g_ys2);
    cudaGetSymbolAddress((void**)&p_fused, g_fused);
    cudaGetSymbolAddress((void**)&p_ctx, g_ctx);
    cudaGetSymbolAddress((void**)&p_h, g_h);
    cudaGetSymbolAddress((void**)&p_mmin, g_mmin);
    cudaGetSymbolAddress((void**)&p_preln, g_preln);

    softmax3_kernel<<<1, 1>>>(scale_w);

    // 1) xz = x @ in_proj_w   (16384 x 4096, K=1024)
    {
        dim3 grid(2 * DI / 128, ROWS_FULL / 128);
        tgemm_kernel<0><<<grid, 256>>>(x, in_proj, p_xz, ROWS_FULL, 2 * DI, DIM,
                                       nullptr, nullptr);
    }

    // 2) per-scale SSM path (downsample fused into conv / ssm_pw)
    float* ys_bufs[NSCALES] = {p_ys0, p_ys1, p_ys2};
    for (int s = 0; s < NSCALES; s++) {
        int stride = 1 << s;
        int Ts = T_LEN / stride;
        int rows = BATCH * Ts;
        int total = rows * DI;
        conv_silu_kernel<<<(total + 255) / 256, 256>>>(p_xz,
                                                       conv_w + (size_t)s * DI * KCONV,
                                                       conv_b + (size_t)s * DI,
                                                       p_xc, Ts, stride);
        bssm_kernel<<<rows / 64, 256>>>(p_xc, xproj_w + (size_t)s * DI * 2 * DSTATE, p_bssm);
        ssm_pw_kernel<<<rows, 256>>>(p_xc, p_bssm,
                                     dtproj_w + (size_t)s * DSTATE * DI,
                                     dtproj_b + (size_t)s * DI,
                                     D_param + (size_t)s * DI,
                                     p_xz, Ts, stride, ys_bufs[s]);
    }

    // 2b) merged upsample + fuse
    {
        int total4 = ROWS_FULL * (DI / 4);
        ups_fuse_kernel<<<(total4 + 255) / 256, 256>>>(p_ys0, p_ys1, p_ys2, p_fused, p_ctx);
    }

    // 3) h = silu(ctx @ cg_w1)   (16384 x 1024, K=2048)
    {
        dim3 grid((DI / 2) / 128, ROWS_FULL / 128);
        tgemm_kernel<1><<<grid, 256>>>(p_ctx, cg_w1, p_h, ROWS_FULL, DI / 2, DI,
                                       nullptr, nullptr);
    }
    // 4) mm_in = fused * sigmoid(h @ cg_w2) * silu(gate)  (16384 x 2048, K=1024)
    {
        dim3 grid(DI / 128, ROWS_FULL / 128);
        tgemm_kernel<2><<<grid, 256>>>(p_h, cg_w2, p_mmin, ROWS_FULL, DI, DI / 2,
                                       p_fused, p_xz + DI);
    }
    // 5) preln = mm_in @ out_proj + x   (16384 x 1024, K=2048)
    {
        dim3 grid(DIM / 128, ROWS_FULL / 128);
        tgemm_kernel<3><<<grid, 256>>>(p_mmin, out_proj, p_preln, ROWS_FULL, DIM, DI,
                                       x, nullptr);
    }
    // 6) LayerNorm -> out
    ln_kernel<<<ROWS_FULL, 256>>>(p_preln, ln_g, ln_b, out);
}

// round 10
// speedup vs baseline: 1.3075x; 1.2204x over previous
#include <cuda_runtime.h>
#include <cuda_bf16.h>
#include <math.h>
#include <stdint.h>

// ---------------- problem constants ----------------
#define BATCH 4
#define T_LEN 4096
#define DIM 1024
#define DI 2048            // d_inner
#define DSTATE 16
#define KCONV 4
#define NSCALES 3
#define ROWS_FULL (BATCH * T_LEN)          // 16384
#define LN_EPS 1e-5f
#define NSPLIT 4           // bssm K-split factor

// ---------------- scratch (__device__ globals; no allocation allowed) ------
__device__ __align__(16) float g_xz[ROWS_FULL * 2 * DI];        // (x_in | gate)
__device__ __align__(16) float g_xs[ROWS_FULL * DI / 2];        // downsampled input
__device__ __align__(16) float g_xc[ROWS_FULL * DI];            // conv+silu output
__device__ __align__(16) float g_bssm[NSPLIT * ROWS_FULL * DSTATE];  // K-split partials
__device__ __align__(16) float g_ys0[ROWS_FULL * DI];           // scale 0 ssm out
__device__ __align__(16) float g_ys1[(ROWS_FULL / 2) * DI];     // scale 1
__device__ __align__(16) float g_ys2[(ROWS_FULL / 4) * DI];     // scale 2
__device__ __align__(16) float g_fused[ROWS_FULL * DI];
__device__ __align__(16) float g_ctx[ROWS_FULL * DI];
__device__ __align__(16) float g_h[ROWS_FULL * (DI / 2)];
__device__ __align__(16) float g_mmin[ROWS_FULL * DI];
__device__ __align__(16) float g_preln[ROWS_FULL * DIM];
__device__ float g_sw[NSCALES];

// ---------------- helpers ----------------
__device__ __forceinline__ float sigmoidf(float x) { return 1.f / (1.f + expf(-x)); }
__device__ __forceinline__ float siluf(float x)    { return x / (1.f + expf(-x)); }
__device__ __forceinline__ float softplusf(float x){ return x > 20.f ? x : log1pf(expf(x)); }

__device__ __forceinline__ uint32_t f2tf32(float f) {
    uint32_t u;
    asm("cvt.rna.tf32.f32 %0, %1;" : "=r"(u) : "f"(f));
    return u;
}

__device__ __forceinline__ void mma_tf32(float* c, const uint32_t* a, uint32_t b0, uint32_t b1) {
    asm volatile(
        "mma.sync.aligned.m16n8k8.row.col.f32.tf32.tf32.f32 "
        "{%0,%1,%2,%3}, {%4,%5,%6,%7}, {%8,%9}, {%0,%1,%2,%3};\n"
        : "+f"(c[0]), "+f"(c[1]), "+f"(c[2]), "+f"(c[3])
        : "r"(a[0]), "r"(a[1]), "r"(a[2]), "r"(a[3]), "r"(b0), "r"(b1));
}

// ---------------- softmax over 3 scale weights ----------------
__global__ void softmax3_kernel(const float* __restrict__ sw) {
    float a = sw[0], b = sw[1], c = sw[2];
    float m = fmaxf(a, fmaxf(b, c));
    float ea = expf(a - m), eb = expf(b - m), ec = expf(c - m);
    float inv = 1.f / (ea + eb + ec);
    g_sw[0] = ea * inv; g_sw[1] = eb * inv; g_sw[2] = ec * inv;
}

// ---------------- TF32 tensor-core GEMM with fused epilogues (R4 verbatim) --
// C[M,N] = A[M,K] * B[K,N], row-major. M%128==0, N%128==0, K%32==0.
// Block tile 128x128, K-tile 32, 256 threads = 8 warps of 64(m)x32(n).
// EPI: 0=store, 1=silu, 2=sigmoid(acc)*e1[row*N+col]*silu(e2[row*4096+col]),
//      3=acc + e1[row*N+col]
template<int EPI>
__global__ __launch_bounds__(256)
void tgemm_kernel(const float* __restrict__ A, const float* __restrict__ B,
                  float* __restrict__ C, int M, int N, int K,
                  const float* __restrict__ e1, const float* __restrict__ e2) {
    // A: [mi(8)][ki(4)][lane(33 pad)][slot(4)]  (fragment-ready, tf32 bits)
    __shared__ __align__(16) uint32_t Asm[8 * 4 * 33 * 4];
    // B: [ni(16)][ki2(2)][lane(32)][q(4)] with XOR swizzle on lane/q by ni
    __shared__ __align__(16) uint32_t Bsm[16 * 256];

    const int tid  = threadIdx.x;
    const int warp = tid >> 5;
    const int lane = tid & 31;
    const int wm = warp >> 2;          // 0..1 (64 rows each)
    const int wn = warp & 3;           // 0..3 (32 cols each)
    const int g  = lane >> 2;          // 0..7
    const int tg = lane & 3;           // 0..3

    const int m0 = blockIdx.y * 128;
    const int n0 = blockIdx.x * 128;

    float acc[4][4][4];
#pragma unroll
    for (int i = 0; i < 4; i++)
#pragma unroll
        for (int j = 0; j < 4; j++)
#pragma unroll
            for (int q = 0; q < 4; q++) acc[i][j][q] = 0.f;

    float4 a_pre[4], b_pre[4];

    // preload tile 0
#pragma unroll
    for (int it = 0; it < 4; it++) {
        int v = tid + it * 256;
        int r = v >> 3, c4 = (v & 7) * 4;
        a_pre[it] = *(const float4*)&A[(size_t)(m0 + r) * K + c4];
        int kk = v >> 5, n4 = (v & 31) * 4;
        b_pre[it] = *(const float4*)&B[(size_t)kk * N + n0 + n4];
    }

    for (int k0 = 0; k0 < K; k0 += 32) {
        // ---- scatter prefetched tile into fragment-ready smem ----
#pragma unroll
        for (int it = 0; it < 4; it++) {
            int v = tid + it * 256;
            {
                int r = v >> 3, c4 = (v & 7) * 4;
                float va[4] = {a_pre[it].x, a_pre[it].y, a_pre[it].z, a_pre[it].w};
#pragma unroll
                for (int j = 0; j < 4; j++) {
                    int c = c4 + j;
                    int mi = r >> 4, rr = r & 15, ki = c >> 3, cc = c & 7;
                    int ls = (rr & 7) * 4 + (cc & 3);
                    int slot = (cc >> 2) * 2 + (rr >> 3);
                    Asm[((mi * 4 + ki) * 33 + ls) * 4 + slot] = f2tf32(va[j]);
                }
            }
            {
                int kk = v >> 5, n4 = (v & 31) * 4;
                float vb[4] = {b_pre[it].x, b_pre[it].y, b_pre[it].z, b_pre[it].w};
#pragma unroll
                for (int j = 0; j < 4; j++) {
                    int nn = n4 + j;
                    int ni = nn >> 3, cc = nn & 7;
                    int ls = cc * 4 + (kk & 3);
                    int ki = kk >> 3;
                    int q = (ki & 1) * 2 + ((kk & 7) >> 2);
                    int lp = ls ^ (ni & 15);
                    int qp = q ^ (ni & 3);
                    Bsm[ni * 256 + (ki >> 1) * 128 + lp * 4 + qp] = f2tf32(vb[j]);
                }
            }
        }
        __syncthreads();

        // ---- prefetch next tile ----
        if (k0 + 32 < K) {
#pragma unroll
            for (int it = 0; it < 4; it++) {
                int v = tid + it * 256;
                int r = v >> 3, c4 = (v & 7) * 4;
                a_pre[it] = *(const float4*)&A[(size_t)(m0 + r) * K + (k0 + 32) + c4];
                int kk = v >> 5, n4 = (v & 31) * 4;
                b_pre[it] = *(const float4*)&B[(size_t)(k0 + 32 + kk) * N + n0 + n4];
            }
        }

        // ---- compute ----
#pragma unroll
        for (int ki2 = 0; ki2 < 2; ki2++) {
            uint32_t bq[4][4];
#pragma unroll
            for (int ni = 0; ni < 4; ni++) {
                int ni_g = wn * 4 + ni;
                int lp = lane ^ (ni_g & 15);
                *(uint4*)bq[ni] = *(const uint4*)&Bsm[ni_g * 256 + ki2 * 128 + lp * 4];
            }
#pragma unroll
            for (int h = 0; h < 2; h++) {
                int ki = ki2 * 2 + h;
                uint32_t af[4][4];
#pragma unroll
                for (int mi = 0; mi < 4; mi++) {
                    int mi_g = wm * 4 + mi;
                    *(uint4*)af[mi] = *(const uint4*)&Asm[((mi_g * 4 + ki) * 33 + lane) * 4];
                }
#pragma unroll
                for (int mi = 0; mi < 4; mi++)
#pragma unroll
                    for (int ni = 0; ni < 4; ni++) {
                        const int p = ni & 3;   // (wn*4+ni)&3 == ni&3, compile-time
                        uint32_t b0 = bq[ni][(h * 2 + 0) ^ p];
                        uint32_t b1 = bq[ni][(h * 2 + 1) ^ p];
                        mma_tf32(acc[mi][ni], af[mi], b0, b1);
                    }
            }
        }
        __syncthreads();
    }

    // ---- epilogue ----
#pragma unroll
    for (int mi = 0; mi < 4; mi++) {
#pragma unroll
        for (int ni = 0; ni < 4; ni++) {
            int r0 = m0 + wm * 64 + mi * 16 + g;
            int cb = n0 + wn * 32 + ni * 8 + tg * 2;
#pragma unroll
            for (int half = 0; half < 2; half++) {
                int row = r0 + half * 8;
                float v0 = acc[mi][ni][half * 2 + 0];
                float v1 = acc[mi][ni][half * 2 + 1];
                size_t idx = (size_t)row * N + cb;
                float o0, o1;
                if (EPI == 0) {
                    o0 = v0; o1 = v1;
                } else if (EPI == 1) {
                    o0 = siluf(v0); o1 = siluf(v1);
                } else if (EPI == 2) {
                    float g0 = e2[(size_t)row * (2 * DI) + cb];
                    float g1 = e2[(size_t)row * (2 * DI) + cb + 1];
                    o0 = e1[idx] * sigmoidf(v0) * siluf(g0);
                    o1 = e1[idx + 1] * sigmoidf(v1) * siluf(g1);
                } else {
                    o0 = v0 + e1[idx];
                    o1 = v1 + e1[idx + 1];
                }
                *(float2*)&C[idx] = make_float2(o0, o1);
            }
        }
    }
}

// ---------------- downsample (mean pool over time), float4 ----------------
__global__ void downsample_kernel(const float* __restrict__ xz, float* __restrict__ xs,
                                  int Ts, int stride) {
    int idx = blockIdx.x * blockDim.x + threadIdx.x;
    int total = BATCH * Ts * (DI / 4);
    if (idx >= total) return;
    int c4 = (idx & (DI / 4 - 1)) * 4;
    int rt = idx / (DI / 4);
    int t = rt % Ts;
    int bb = rt / Ts;
    float4 acc = make_float4(0.f, 0.f, 0.f, 0.f);
    for (int r = 0; r < stride; r++) {
        float4 v = *(const float4*)&xz[(size_t)(bb * T_LEN + t * stride + r) * (2 * DI) + c4];
        acc.x += v.x; acc.y += v.y; acc.z += v.z; acc.w += v.w;
    }
    float inv = 1.f / (float)stride;
    acc.x *= inv; acc.y *= inv; acc.z *= inv; acc.w *= inv;
    *(float4*)&xs[(size_t)(bb * Ts + t) * DI + c4] = acc;
}

// ---------------- causal depthwise conv (K=4) + silu, float4 ----------------
__global__ void conv_silu_kernel(const float* __restrict__ x, int ld,
                                 const float* __restrict__ w, const float* __restrict__ b,
                                 float* __restrict__ xc, int Ts) {
    int idx = blockIdx.x * blockDim.x + threadIdx.x;
    int total = BATCH * Ts * (DI / 4);
    if (idx >= total) return;
    int c4 = (idx & (DI / 4 - 1)) * 4;
    int rt = idx / (DI / 4);
    int t = rt % Ts;
    int bb = rt / Ts;
    // weights for 4 channels: w[c][k], c row-major with stride KCONV
    float4 w0 = *(const float4*)&w[(c4 + 0) * KCONV];
    float4 w1 = *(const float4*)&w[(c4 + 1) * KCONV];
    float4 w2 = *(const float4*)&w[(c4 + 2) * KCONV];
    float4 w3 = *(const float4*)&w[(c4 + 3) * KCONV];
    float4 acc = *(const float4*)&b[c4];
    const float wk[4][4] = {{w0.x, w0.y, w0.z, w0.w}, {w1.x, w1.y, w1.z, w1.w},
                            {w2.x, w2.y, w2.z, w2.w}, {w3.x, w3.y, w3.z, w3.w}};
#pragma unroll
    for (int k = 0; k < KCONV; k++) {
        int tt = t - (KCONV - 1) + k;
        if (tt >= 0) {
            float4 v = *(const float4*)&x[(size_t)(bb * Ts + tt) * ld + c4];
            acc.x = fmaf(wk[0][k], v.x, acc.x);
            acc.y = fmaf(wk[1][k], v.y, acc.y);
            acc.z = fmaf(wk[2][k], v.z, acc.z);
            acc.w = fmaf(wk[3][k], v.w, acc.w);
        }
    }
    acc.x = siluf(acc.x); acc.y = siluf(acc.y);
    acc.z = siluf(acc.z); acc.w = siluf(acc.w);
    *(float4*)&xc[(size_t)rt * DI + c4] = acc;
}

// ---------------- B_ssm partials = xc @ xproj[:, :16], K-split ---------------
// grid = (rows/64, NSPLIT). Block 256: thread (r 0..63, jq 0..3) -> 4 cols.
// Inner iter: 1 LDS.32 (broadcast x4) + 1 LDS.128 + 4 FMA.
__global__ __launch_bounds__(256)
void bssm_kernel(const float* __restrict__ xc, const float* __restrict__ xproj,
                 float* __restrict__ bssm_p, int rows) {
    __shared__ float xs[64 * 68];                 // row stride 68: conflict-free
    __shared__ __align__(16) float ws[64 * 16];
    const int tid = threadIdx.x;
    const int row0 = blockIdx.x * 64;
    const int ks0 = blockIdx.y * (DI / NSPLIT);   // 512-wide K chunk
    const int r  = tid >> 2;
    const int jq = tid & 3;
    float acc[4] = {0.f, 0.f, 0.f, 0.f};

    for (int k0 = ks0; k0 < ks0 + DI / NSPLIT; k0 += 64) {
#pragma unroll
        for (int i = 0; i < 4; i++) {
            int v = tid + i * 256;
            int lr = v >> 4, c4 = (v & 15) * 4;
            *(float4*)&xs[lr * 68 + c4] = *(const float4*)&xc[(size_t)(row0 + lr) * DI + k0 + c4];
        }
        {
            int kk = tid >> 4, j = tid & 15;      // 256 threads cover 16x16; x4 rows
#pragma unroll
            for (int i = 0; i < 4; i++)
                ws[(kk + i * 16) * 16 + j] = xproj[(size_t)(k0 + kk + i * 16) * (2 * DSTATE) + j];
        }
        __syncthreads();
#pragma unroll 16
        for (int kk = 0; kk < 64; kk++) {
            float xv = xs[r * 68 + kk];
            float4 w4 = *(const float4*)&ws[kk * 16 + jq * 4];
            acc[0] = fmaf(xv, w4.x, acc[0]);
            acc[1] = fmaf(xv, w4.y, acc[1]);
            acc[2] = fmaf(xv, w4.z, acc[2]);
            acc[3] = fmaf(xv, w4.w, acc[3]);
        }
        __syncthreads();
    }
    size_t o = ((size_t)blockIdx.y * rows + row0 + r) * DSTATE + jq * 4;
    *(float4*)&bssm_p[o] = *(float4*)acc;
}

// ---------------- SSM pointwise, float4, sums K-split partials --------------
__global__ __launch_bounds__(256)
void ssm_pw_kernel(const float* __restrict__ xc, const float* __restrict__ bssm_p,
                   const float* __restrict__ dtw, const float* __restrict__ dtb,
                   const float* __restrict__ D, const float* __restrict__ xs, int ld,
                   float* __restrict__ ys, int rows) {
    int row = blockIdx.x;
    __shared__ float bs[DSTATE];
    if (threadIdx.x < DSTATE) {
        float v = 0.f;
#pragma unroll
        for (int sp = 0; sp < NSPLIT; sp++)
            v += bssm_p[((size_t)sp * rows + row) * DSTATE + threadIdx.x];
        bs[threadIdx.x] = v;
    }
    __syncthreads();
    for (int cq = threadIdx.x; cq < DI / 4; cq += 256) {
        int c4 = cq * 4;
        float4 dt = *(const float4*)&dtb[c4];
#pragma unroll
        for (int k = 0; k < DSTATE; k++) {
            float bk = bs[k];
            float4 wv = *(const float4*)&dtw[k * DI + c4];
            dt.x = fmaf(bk, wv.x, dt.x);
            dt.y = fmaf(bk, wv.y, dt.y);
            dt.z = fmaf(bk, wv.z, dt.z);
            dt.w = fmaf(bk, wv.w, dt.w);
        }
        float4 xcv = *(const float4*)&xc[(size_t)row * DI + c4];
        float4 xv  = *(const float4*)&xs[(size_t)row * ld + c4];
        float4 Dv  = *(const float4*)&D[c4];
        float4 o;
        o.x = xcv.x * sigmoidf(softplusf(dt.x)) + Dv.x * xv.x;
        o.y = xcv.y * sigmoidf(softplusf(dt.y)) + Dv.y * xv.y;
        o.z = xcv.z * sigmoidf(softplusf(dt.z)) + Dv.z * xv.z;
        o.w = xcv.w * sigmoidf(softplusf(dt.w)) + Dv.w * xv.w;
        *(float4*)&ys[(size_t)row * DI + c4] = o;
    }
}

// ---------------- merged upsample + fuse (all 3 scales in one pass) ----------
__global__ void ups_fuse_kernel(const float* __restrict__ ys0,
                                const float* __restrict__ ys1,
                                const float* __restrict__ ys2,
                                float* __restrict__ fused, float* __restrict__ ctx) {
    int idx = blockIdx.x * blockDim.x + threadIdx.x;
    const int total4 = ROWS_FULL * (DI / 4);
    if (idx >= total4) return;
    int c4 = (idx & (DI / 4 - 1)) * 4;
    int rt = idx / (DI / 4);
    int t = rt % T_LEN;
    int bb = rt / T_LEN;

    float4 v0 = *(const float4*)&ys0[(size_t)(bb * T_LEN + t) * DI + c4];

    float4 v1, v2;
    {   // scale 1: Ts = 2048
        const int Ts = T_LEN / 2;
        float coord = (t + 0.5f) * 0.5f - 0.5f;
        coord = fminf(fmaxf(coord, 0.f), (float)(Ts - 1));
        int lo = (int)floorf(coord);
        int hi = min(lo + 1, Ts - 1);
        float wf = coord - (float)lo;
        float4 a = *(const float4*)&ys1[(size_t)(bb * Ts + lo) * DI + c4];
        float4 b = *(const float4*)&ys1[(size_t)(bb * Ts + hi) * DI + c4];
        v1.x = a.x + (b.x - a.x) * wf; v1.y = a.y + (b.y - a.y) * wf;
        v1.z = a.z + (b.z - a.z) * wf; v1.w = a.w + (b.w - a.w) * wf;
    }
    {   // scale 2: Ts = 1024
        const int Ts = T_LEN / 4;
        float coord = (t + 0.5f) * 0.25f - 0.5f;
        coord = fminf(fmaxf(coord, 0.f), (float)(Ts - 1));
        int lo = (int)floorf(coord);
        int hi = min(lo + 1, Ts - 1);
        float wf = coord - (float)lo;
        float4 a = *(const float4*)&ys2[(size_t)(bb * Ts + lo) * DI + c4];
        float4 b = *(const float4*)&ys2[(size_t)(bb * Ts + hi) * DI + c4];
        v2.x = a.x + (b.x - a.x) * wf; v2.y = a.y + (b.y - a.y) * wf;
        v2.z = a.z + (b.z - a.z) * wf; v2.w = a.w + (b.w - a.w) * wf;
    }

    float w0 = g_sw[0], w1 = g_sw[1], w2 = g_sw[2];
    float4 f, cx;
    f.x = w0 * v0.x + w1 * v1.x + w2 * v2.x;
    f.y = w0 * v0.y + w1 * v1.y + w2 * v2.y;
    f.z = w0 * v0.z + w1 * v1.z + w2 * v2.z;
    f.w = w0 * v0.w + w1 * v1.w + w2 * v2.w;
    const float third = 1.f / 3.f;
    cx.x = (v0.x + v1.x + v2.x) * third;
    cx.y = (v0.y + v1.y + v2.y) * third;
    cx.z = (v0.z + v1.z + v2.z) * third;
    cx.w = (v0.w + v1.w + v2.w) * third;

    size_t o = (size_t)rt * DI + c4;
    *(float4*)&fused[o] = f;
    *(float4*)&ctx[o] = cx;
}

// ---------------- LayerNorm over last dim (1024), float4 ----------------
__global__ __launch_bounds__(256)
void ln_kernel(const float* __restrict__ y, const float* __restrict__ g,
               const float* __restrict__ b, float* __restrict__ out) {
    int row = blockIdx.x;
    const float* yr = y + (size_t)row * DIM;
    int c4 = threadIdx.x * 4;
    float4 v = *(const float4*)&yr[c4];
    float s  = v.x + v.y + v.z + v.w;
    float s2 = v.x * v.x + v.y * v.y + v.z * v.z + v.w * v.w;
#pragma unroll
    for (int o = 16; o > 0; o >>= 1) {
        s  += __shfl_down_sync(0xffffffffu, s, o);
        s2 += __shfl_down_sync(0xffffffffu, s2, o);
    }
    __shared__ float shs[8], shs2[8];
    __shared__ float smu, srstd;
    int wid = threadIdx.x >> 5, lane = threadIdx.x & 31;
    if (lane == 0) { shs[wid] = s; shs2[wid] = s2; }
    __syncthreads();
    if (wid == 0) {
        s  = lane < 8 ? shs[lane]  : 0.f;
        s2 = lane < 8 ? shs2[lane] : 0.f;
#pragma unroll
        for (int o = 4; o > 0; o >>= 1) {
            s  += __shfl_down_sync(0xffffffffu, s, o);
            s2 += __shfl_down_sync(0xffffffffu, s2, o);
        }
        if (lane == 0) {
            float mu = s / DIM;
            float var = s2 / DIM - mu * mu;
            smu = mu;
            srstd = rsqrtf(var + LN_EPS);
        }
    }
    __syncthreads();
    float mu = smu, rstd = srstd;
    float4 gv = *(const float4*)&g[c4];
    float4 bv = *(const float4*)&b[c4];
    float4 o;
    o.x = (v.x - mu) * rstd * gv.x + bv.x;
    o.y = (v.y - mu) * rstd * gv.y + bv.y;
    o.z = (v.z - mu) * rstd * gv.z + bv.z;
    o.w = (v.w - mu) * rstd * gv.w + bv.w;
    *(float4*)&out[(size_t)row * DIM + c4] = o;
}

// ---------------- launch ----------------
extern "C" void kernel_launch(void* const* d_in, const int* in_sizes, int n_in,
                              void* d_out, int out_size) {
    const float* x        = (const float*)d_in[0];
    const float* in_proj  = (const float*)d_in[1];
    const float* conv_w   = (const float*)d_in[2];
    const float* conv_b   = (const float*)d_in[3];
    const float* xproj_w  = (const float*)d_in[4];
    const float* dtproj_w = (const float*)d_in[5];
    const float* dtproj_b = (const float*)d_in[6];
    const float* D_param  = (const float*)d_in[7];
    const float* scale_w  = (const float*)d_in[8];
    const float* cg_w1    = (const float*)d_in[9];
    const float* cg_w2    = (const float*)d_in[10];
    const float* out_proj = (const float*)d_in[11];
    const float* ln_g     = (const float*)d_in[12];
    const float* ln_b     = (const float*)d_in[13];
    float* out = (float*)d_out;

    float *p_xz, *p_xs, *p_xc, *p_bssm, *p_ys0, *p_ys1, *p_ys2,
          *p_fused, *p_ctx, *p_h, *p_mmin, *p_preln;
    cudaGetSymbolAddress((void**)&p_xz, g_xz);
    cudaGetSymbolAddress((void**)&p_xs, g_xs);
    cudaGetSymbolAddress((void**)&p_xc, g_xc);
    cudaGetSymbolAddress((void**)&p_bssm, g_bssm);
    cudaGetSymbolAddress((void**)&p_ys0, g_ys0);
    cudaGetSymbolAddress((void**)&p_ys1, g_ys1);
    cudaGetSymbolAddress((void**)&p_ys2, g_ys2);
    cudaGetSymbolAddress((void**)&p_fused, g_fused);
    cudaGetSymbolAddress((void**)&p_ctx, g_ctx);
    cudaGetSymbolAddress((void**)&p_h, g_h);
    cudaGetSymbolAddress((void**)&p_mmin, g_mmin);
    cudaGetSymbolAddress((void**)&p_preln, g_preln);

    softmax3_kernel<<<1, 1>>>(scale_w);

    // 1) xz = x @ in_proj_w   (16384 x 4096, K=1024)
    {
        dim3 grid(2 * DI / 128, ROWS_FULL / 128);
        tgemm_kernel<0><<<grid, 256>>>(x, in_proj, p_xz, ROWS_FULL, 2 * DI, DIM,
                                       nullptr, nullptr);
    }

    // 2) per-scale SSM path
    float* ys_bufs[NSCALES] = {p_ys0, p_ys1, p_ys2};
    for (int s = 0; s < NSCALES; s++) {
        int stride = 1 << s;
        int Ts = T_LEN / stride;
        int rows = BATCH * Ts;
        int total4 = rows * (DI / 4);
        const float* xin;
        int ld;
        if (s == 0) {
            xin = p_xz; ld = 2 * DI;
        } else {
            downsample_kernel<<<(total4 + 255) / 256, 256>>>(p_xz, p_xs, Ts, stride);
            xin = p_xs; ld = DI;
        }
        conv_silu_kernel<<<(total4 + 255) / 256, 256>>>(xin, ld,
                                                        conv_w + (size_t)s * DI * KCONV,
                                                        conv_b + (size_t)s * DI,
                                                        p_xc, Ts);
        {
            dim3 bgrid(rows / 64, NSPLIT);
            bssm_kernel<<<bgrid, 256>>>(p_xc, xproj_w + (size_t)s * DI * 2 * DSTATE,
                                        p_bssm, rows);
        }
        ssm_pw_kernel<<<rows, 256>>>(p_xc, p_bssm,
                                     dtproj_w + (size_t)s * DSTATE * DI,
                                     dtproj_b + (size_t)s * DI,
                                     D_param + (size_t)s * DI,
                                     xin, ld, ys_bufs[s], rows);
    }

    // 2b) merged upsample + fuse
    {
        int total4 = ROWS_FULL * (DI / 4);
        ups_fuse_kernel<<<(total4 + 255) / 256, 256>>>(p_ys0, p_ys1, p_ys2, p_fused, p_ctx);
    }

    // 3) h = silu(ctx @ cg_w1)   (16384 x 1024, K=2048)
    {
        dim3 grid((DI / 2) / 128, ROWS_FULL / 128);
        tgemm_kernel<1><<<grid, 256>>>(p_ctx, cg_w1, p_h, ROWS_FULL, DI / 2, DI,
                                       nullptr, nullptr);
    }
    // 4) mm_in = fused * sigmoid(h @ cg_w2) * silu(gate)  (16384 x 2048, K=1024)
    {
        dim3 grid(DI / 128, ROWS_FULL / 128);
        tgemm_kernel<2><<<grid, 256>>>(p_h, cg_w2, p_mmin, ROWS_FULL, DI, DI / 2,
                                       p_fused, p_xz + DI);
    }
    // 5) preln = mm_in @ out_proj + x   (16384 x 1024, K=2048)
    {
        dim3 grid(DIM / 128, ROWS_FULL / 128);
        tgemm_kernel<3><<<grid, 256>>>(p_mmin, out_proj, p_preln, ROWS_FULL, DIM, DI,
                                       x, nullptr);
    }
    // 6) LayerNorm -> out
    ln_kernel<<<ROWS_FULL, 256>>>(p_preln, ln_g, ln_b, out);
}

// round 13
// speedup vs baseline: 2.2955x; 1.7556x over previous
#include <cuda_runtime.h>
#include <cuda_fp16.h>
#include <math.h>
#include <stdint.h>

// ---------------- problem constants ----------------
#define BATCH 4
#define T_LEN 4096
#define DIM 1024
#define DI 2048            // d_inner
#define DSTATE 16
#define KCONV 4
#define NSCALES 3
#define ROWS_FULL (BATCH * T_LEN)          // 16384
#define LN_EPS 1e-5f
#define NSPLIT 4           // bssm K-split factor

// ---------------- scratch (__device__ globals; no allocation allowed) ------
__device__ __align__(16) float g_xz[ROWS_FULL * 2 * DI];        // (x_in | gate)
__device__ __align__(16) float g_xs[ROWS_FULL * DI / 2];        // downsampled input
__device__ __align__(16) float g_xc[ROWS_FULL * DI];            // conv+silu output
__device__ __align__(16) float g_bssm[NSPLIT * ROWS_FULL * DSTATE];  // K-split partials
__device__ __align__(16) float g_ys0[ROWS_FULL * DI];
__device__ __align__(16) float g_ys1[(ROWS_FULL / 2) * DI];
__device__ __align__(16) float g_ys2[(ROWS_FULL / 4) * DI];
__device__ __align__(16) float g_fused[ROWS_FULL * DI];
__device__ __align__(16) float g_ctx[ROWS_FULL * DI];
__device__ __align__(16) float g_h[ROWS_FULL * (DI / 2)];
__device__ __align__(16) float g_mmin[ROWS_FULL * DI];
__device__ __align__(16) float g_preln[ROWS_FULL * DIM];
// half2 (k-paired) weight copies: in_proj | cg_w1 | cg_w2 | out_proj
__device__ __align__(16) uint32_t g_wh[5242880];
__device__ float g_sw[NSCALES];

// ---------------- helpers ----------------
__device__ __forceinline__ float sigmoidf(float x) { return 1.f / (1.f + expf(-x)); }
__device__ __forceinline__ float siluf(float x)    { return x / (1.f + expf(-x)); }
__device__ __forceinline__ float softplusf(float x){ return x > 20.f ? x : log1pf(expf(x)); }

__device__ __forceinline__ uint32_t pack_h2(float lo, float hi) {
    __half2 h = __floats2half2_rn(lo, hi);
    return *(uint32_t*)&h;
}

__device__ __forceinline__ void mma_f16(float* c, const uint32_t* a, uint32_t b0, uint32_t b1) {
    asm volatile(
        "mma.sync.aligned.m16n8k16.row.col.f32.f16.f16.f32 "
        "{%0,%1,%2,%3}, {%4,%5,%6,%7}, {%8,%9}, {%0,%1,%2,%3};\n"
        : "+f"(c[0]), "+f"(c[1]), "+f"(c[2]), "+f"(c[3])
        : "r"(a[0]), "r"(a[1]), "r"(a[2]), "r"(a[3]), "r"(b0), "r"(b1));
}

// ---------------- softmax over 3 scale weights ----------------
__global__ void softmax3_kernel(const float* __restrict__ sw) {
    float a = sw[0], b = sw[1], c = sw[2];
    float m = fmaxf(a, fmaxf(b, c));
    float ea = expf(a - m), eb = expf(b - m), ec = expf(c - m);
    float inv = 1.f / (ea + eb + ec);
    g_sw[0] = ea * inv; g_sw[1] = eb * inv; g_sw[2] = ec * inv;
}

// ---------------- weight preconvert: W[K][N] f32 -> Wh2[K/2][N] half2 -------
__global__ void cvt_h2_kernel(const float* __restrict__ in, uint32_t* __restrict__ out,
                              int Kh, int N) {
    int i = blockIdx.x * blockDim.x + threadIdx.x;
    int total = Kh * N;
    if (i >= total) return;
    int p = i / N, n = i - p * N;
    float a = in[(size_t)(2 * p) * N + n];
    float b = in[(size_t)(2 * p + 1) * N + n];
    out[(size_t)p * N + n] = pack_h2(a, b);
}

// ---------------- FP16 tensor-core GEMM with fused epilogues ----------------
// C[M,N] = A[M,K](f32) * Bh2[K/2][N](half2 k-paired), row-major.
// M%128==0, N%128==0, K%32==0. Block tile 128x128, K-tile 32 (2 k16 steps),
// 256 threads = 8 warps of 64(m)x32(n). fp32 accumulate.
// EPI: 0=store, 1=silu, 2=sigmoid(acc)*e1[row*N+col]*silu(e2[row*4096+col]),
//      3=acc + e1[row*N+col]
#define A_GRP 132   // u32 stride per (mi,kstep) fragment group (128 + 4 pad)
#define B_GRP 130   // u32 stride per ni group (2*64 + 2 pad)

template<int EPI>
__global__ __launch_bounds__(256)
void tgemm_kernel(const float* __restrict__ A, const uint32_t* __restrict__ Bh,
                  float* __restrict__ C, int M, int N, int K,
                  const float* __restrict__ e1, const float* __restrict__ e2) {
    // A: [mi(8)*kstep(2)][lane(32)][slot(4)] half2, fragment-ready
    __shared__ __align__(16) uint32_t Asm[16 * A_GRP];
    // B: [ni(16)][kstep(2)][ls(32)][slot(2)] half2, fragment-ready
    __shared__ __align__(16) uint32_t Bsm[16 * B_GRP];

    const int tid  = threadIdx.x;
    const int warp = tid >> 5;
    const int lane = tid & 31;
    const int wm = warp >> 2;          // 0..1 (64 rows each)
    const int wn = warp & 3;           // 0..3 (32 cols each)
    const int g  = lane >> 2;          // 0..7
    const int tg = lane & 3;           // 0..3

    const int m0 = blockIdx.y * 128;
    const int n0 = blockIdx.x * 128;

    float acc[4][4][4];
#pragma unroll
    for (int i = 0; i < 4; i++)
#pragma unroll
        for (int j = 0; j < 4; j++)
#pragma unroll
            for (int q = 0; q < 4; q++) acc[i][j][q] = 0.f;

    float4 a_pre[4];
    uint4  b_pre[2];

    // preload tile 0
#pragma unroll
    for (int it = 0; it < 4; it++) {
        int v = tid + it * 256;
        int r = v >> 3, c4 = (v & 7) * 4;
        a_pre[it] = *(const float4*)&A[(size_t)(m0 + r) * K + c4];
    }
#pragma unroll
    for (int it = 0; it < 2; it++) {
        int v = tid + it * 256;
        int prow = v >> 5, n4 = (v & 31) * 4;
        b_pre[it] = *(const uint4*)&Bh[(size_t)prow * N + n0 + n4];
    }

    for (int k0 = 0; k0 < K; k0 += 32) {
        // ---- scatter prefetched tile into fragment-ready smem ----
#pragma unroll
        for (int it = 0; it < 4; it++) {
            int v = tid + it * 256;
            int r = v >> 3, c4 = (v & 7) * 4;
            int mi = r >> 4, rr = r & 15;
            float va[4] = {a_pre[it].x, a_pre[it].y, a_pre[it].z, a_pre[it].w};
#pragma unroll
            for (int j = 0; j < 2; j++) {
                int c = c4 + 2 * j;
                int p = (c & 15) >> 1, kstep = c >> 4;
                int ls = (rr & 7) * 4 + (p & 3);
                int slot = (p >> 2) * 2 + (rr >> 3);
                Asm[(mi * 2 + kstep) * A_GRP + ls * 4 + slot] = pack_h2(va[2 * j], va[2 * j + 1]);
            }
        }
#pragma unroll
        for (int it = 0; it < 2; it++) {
            int v = tid + it * 256;
            int prow = v >> 5, n4 = (v & 31) * 4;
            int pp = prow & 7, kstep = prow >> 3;
            uint32_t vb[4] = {b_pre[it].x, b_pre[it].y, b_pre[it].z, b_pre[it].w};
#pragma unroll
            for (int j = 0; j < 4; j++) {
                int nn = n4 + j;
                int ni = nn >> 3, cc = nn & 7;
                int ls = cc * 4 + (pp & 3);
                int slot = pp >> 2;
                Bsm[ni * B_GRP + kstep * 64 + ls * 2 + slot] = vb[j];
            }
        }
        __syncthreads();

        // ---- prefetch next tile ----
        if (k0 + 32 < K) {
#pragma unroll
            for (int it = 0; it < 4; it++) {
                int v = tid + it * 256;
                int r = v >> 3, c4 = (v & 7) * 4;
                a_pre[it] = *(const float4*)&A[(size_t)(m0 + r) * K + (k0 + 32) + c4];
            }
            int ph0 = (k0 + 32) >> 1;
#pragma unroll
            for (int it = 0; it < 2; it++) {
                int v = tid + it * 256;
                int prow = v >> 5, n4 = (v & 31) * 4;
                b_pre[it] = *(const uint4*)&Bh[(size_t)(ph0 + prow) * N + n0 + n4];
            }
        }

        // ---- compute ----
#pragma unroll
        for (int kstep = 0; kstep < 2; kstep++) {
            uint32_t bq[4][2];
#pragma unroll
            for (int nj = 0; nj < 4; nj++) {
                int ni_g = wn * 4 + nj;
                *(uint2*)bq[nj] = *(const uint2*)&Bsm[ni_g * B_GRP + kstep * 64 + lane * 2];
            }
            uint32_t af[4][4];
#pragma unroll
            for (int mi = 0; mi < 4; mi++) {
                int mi_g = wm * 4 + mi;
                *(uint4*)af[mi] = *(const uint4*)&Asm[(mi_g * 2 + kstep) * A_GRP + lane * 4];
            }
#pragma unroll
            for (int mi = 0; mi < 4; mi++)
#pragma unroll
                for (int nj = 0; nj < 4; nj++)
                    mma_f16(acc[mi][nj], af[mi], bq[nj][0], bq[nj][1]);
        }
        __syncthreads();
    }

    // ---- epilogue (same acc layout as m16n8 tf32 version) ----
#pragma unroll
    for (int mi = 0; mi < 4; mi++) {
#pragma unroll
        for (int ni = 0; ni < 4; ni++) {
            int r0 = m0 + wm * 64 + mi * 16 + g;
            int cb = n0 + wn * 32 + ni * 8 + tg * 2;
#pragma unroll
            for (int half = 0; half < 2; half++) {
                int row = r0 + half * 8;
                float v0 = acc[mi][ni][half * 2 + 0];
                float v1 = acc[mi][ni][half * 2 + 1];
                size_t idx = (size_t)row * N + cb;
                float o0, o1;
                if (EPI == 0) {
                    o0 = v0; o1 = v1;
                } else if (EPI == 1) {
                    o0 = siluf(v0); o1 = siluf(v1);
                } else if (EPI == 2) {
                    float g0 = e2[(size_t)row * (2 * DI) + cb];
                    float g1 = e2[(size_t)row * (2 * DI) + cb + 1];
                    o0 = e1[idx] * sigmoidf(v0) * siluf(g0);
                    o1 = e1[idx + 1] * sigmoidf(v1) * siluf(g1);
                } else {
                    o0 = v0 + e1[idx];
                    o1 = v1 + e1[idx + 1];
                }
                *(float2*)&C[idx] = make_float2(o0, o1);
            }
        }
    }
}

// ---------------- downsample (mean pool over time), float4 ----------------
__global__ void downsample_kernel(const float* __restrict__ xz, float* __restrict__ xs,
                                  int Ts, int stride) {
    int idx = blockIdx.x * blockDim.x + threadIdx.x;
    int total = BATCH * Ts * (DI / 4);
    if (idx >= total) return;
    int c4 = (idx & (DI / 4 - 1)) * 4;
    int rt = idx / (DI / 4);
    int t = rt % Ts;
    int bb = rt / Ts;
    float4 acc = make_float4(0.f, 0.f, 0.f, 0.f);
    for (int r = 0; r < stride; r++) {
        float4 v = *(const float4*)&xz[(size_t)(bb * T_LEN + t * stride + r) * (2 * DI) + c4];
        acc.x += v.x; acc.y += v.y; acc.z += v.z; acc.w += v.w;
    }
    float inv = 1.f / (float)stride;
    acc.x *= inv; acc.y *= inv; acc.z *= inv; acc.w *= inv;
    *(float4*)&xs[(size_t)(bb * Ts + t) * DI + c4] = acc;
}

// ---------------- causal depthwise conv (K=4) + silu, float4 ----------------
__global__ void conv_silu_kernel(const float* __restrict__ x, int ld,
                                 const float* __restrict__ w, const float* __restrict__ b,
                                 float* __restrict__ xc, int Ts) {
    int idx = blockIdx.x * blockDim.x + threadIdx.x;
    int total = BATCH * Ts * (DI / 4);
    if (idx >= total) return;
    int c4 = (idx & (DI / 4 - 1)) * 4;
    int rt = idx / (DI / 4);
    int t = rt % Ts;
    int bb = rt / Ts;
    float4 w0 = *(const float4*)&w[(c4 + 0) * KCONV];
    float4 w1 = *(const float4*)&w[(c4 + 1) * KCONV];
    float4 w2 = *(const float4*)&w[(c4 + 2) * KCONV];
    float4 w3 = *(const float4*)&w[(c4 + 3) * KCONV];
    float4 acc = *(const float4*)&b[c4];
    const float wk[4][4] = {{w0.x, w0.y, w0.z, w0.w}, {w1.x, w1.y, w1.z, w1.w},
                            {w2.x, w2.y, w2.z, w2.w}, {w3.x, w3.y, w3.z, w3.w}};
#pragma unroll
    for (int k = 0; k < KCONV; k++) {
        int tt = t - (KCONV - 1) + k;
        if (tt >= 0) {
            float4 v = *(const float4*)&x[(size_t)(bb * Ts + tt) * ld + c4];
            acc.x = fmaf(wk[0][k], v.x, acc.x);
            acc.y = fmaf(wk[1][k], v.y, acc.y);
            acc.z = fmaf(wk[2][k], v.z, acc.z);
            acc.w = fmaf(wk[3][k], v.w, acc.w);
        }
    }
    acc.x = siluf(acc.x); acc.y = siluf(acc.y);
    acc.z = siluf(acc.z); acc.w = siluf(acc.w);
    *(float4*)&xc[(size_t)rt * DI + c4] = acc;
}

// ---------------- B_ssm partials = xc @ xproj[:, :16], K-split ---------------
__global__ __launch_bounds__(256)
void bssm_kernel(const float* __restrict__ xc, const float* __restrict__ xproj,
                 float* __restrict__ bssm_p, int rows) {
    __shared__ float xs[64 * 68];
    __shared__ __align__(16) float ws[64 * 16];
    const int tid = threadIdx.x;
    const int row0 = blockIdx.x * 64;
    const int ks0 = blockIdx.y * (DI / NSPLIT);
    const int r  = tid >> 2;
    const int jq = tid & 3;
    float acc[4] = {0.f, 0.f, 0.f, 0.f};

    for (int k0 = ks0; k0 < ks0 + DI / NSPLIT; k0 += 64) {
#pragma unroll
        for (int i = 0; i < 4; i++) {
            int v = tid + i * 256;
            int lr = v >> 4, c4 = (v & 15) * 4;
            *(float4*)&xs[lr * 68 + c4] = *(const float4*)&xc[(size_t)(row0 + lr) * DI + k0 + c4];
        }
        {
            int kk = tid >> 4, j = tid & 15;
#pragma unroll
            for (int i = 0; i < 4; i++)
                ws[(kk + i * 16) * 16 + j] = xproj[(size_t)(k0 + kk + i * 16) * (2 * DSTATE) + j];
        }
        __syncthreads();
#pragma unroll 16
        for (int kk = 0; kk < 64; kk++) {
            float xv = xs[r * 68 + kk];
            float4 w4 = *(const float4*)&ws[kk * 16 + jq * 4];
            acc[0] = fmaf(xv, w4.x, acc[0]);
            acc[1] = fmaf(xv, w4.y, acc[1]);
            acc[2] = fmaf(xv, w4.z, acc[2]);
            acc[3] = fmaf(xv, w4.w, acc[3]);
        }
        __syncthreads();
    }
    size_t o = ((size_t)blockIdx.y * rows + row0 + r) * DSTATE + jq * 4;
    *(float4*)&bssm_p[o] = *(float4*)acc;
}

// ---------------- SSM pointwise, float4, sums K-split partials --------------
__global__ __launch_bounds__(256)
void ssm_pw_kernel(const float* __restrict__ xc, const float* __restrict__ bssm_p,
                   const float* __restrict__ dtw, const float* __restrict__ dtb,
                   const float* __restrict__ D, const float* __restrict__ xs, int ld,
                   float* __restrict__ ys, int rows) {
    int row = blockIdx.x;
    __shared__ float bs[DSTATE];
    if (threadIdx.x < DSTATE) {
        float v = 0.f;
#pragma unroll
        for (int sp = 0; sp < NSPLIT; sp++)
            v += bssm_p[((size_t)sp * rows + row) * DSTATE + threadIdx.x];
        bs[threadIdx.x] = v;
    }
    __syncthreads();
    for (int cq = threadIdx.x; cq < DI / 4; cq += 256) {
        int c4 = cq * 4;
        float4 dt = *(const float4*)&dtb[c4];
#pragma unroll
        for (int k = 0; k < DSTATE; k++) {
            float bk = bs[k];
            float4 wv = *(const float4*)&dtw[k * DI + c4];
            dt.x = fmaf(bk, wv.x, dt.x);
            dt.y = fmaf(bk, wv.y, dt.y);
            dt.z = fmaf(bk, wv.z, dt.z);
            dt.w = fmaf(bk, wv.w, dt.w);
        }
        float4 xcv = *(const float4*)&xc[(size_t)row * DI + c4];
        float4 xv  = *(const float4*)&xs[(size_t)row * ld + c4];
        float4 Dv  = *(const float4*)&D[c4];
        float4 o;
        o.x = xcv.x * sigmoidf(softplusf(dt.x)) + Dv.x * xv.x;
        o.y = xcv.y * sigmoidf(softplusf(dt.y)) + Dv.y * xv.y;
        o.z = xcv.z * sigmoidf(softplusf(dt.z)) + Dv.z * xv.z;
        o.w = xcv.w * sigmoidf(softplusf(dt.w)) + Dv.w * xv.w;
        *(float4*)&ys[(size_t)row * DI + c4] = o;
    }
}

// ---------------- merged upsample + fuse (all 3 scales in one pass) ----------
__global__ void ups_fuse_kernel(const float* __restrict__ ys0,
                                const float* __restrict__ ys1,
                                const float* __restrict__ ys2,
                                float* __restrict__ fused, float* __restrict__ ctx) {
    int idx = blockIdx.x * blockDim.x + threadIdx.x;
    const int total4 = ROWS_FULL * (DI / 4);
    if (idx >= total4) return;
    int c4 = (idx & (DI / 4 - 1)) * 4;
    int rt = idx / (DI / 4);
    int t = rt % T_LEN;
    int bb = rt / T_LEN;

    float4 v0 = *(const float4*)&ys0[(size_t)(bb * T_LEN + t) * DI + c4];

    float4 v1, v2;
    {
        const int Ts = T_LEN / 2;
        float coord = (t + 0.5f) * 0.5f - 0.5f;
        coord = fminf(fmaxf(coord, 0.f), (float)(Ts - 1));
        int lo = (int)floorf(coord);
        int hi = min(lo + 1, Ts - 1);
        float wf = coord - (float)lo;
        float4 a = *(const float4*)&ys1[(size_t)(bb * Ts + lo) * DI + c4];
        float4 b = *(const float4*)&ys1[(size_t)(bb * Ts + hi) * DI + c4];
        v1.x = a.x + (b.x - a.x) * wf; v1.y = a.y + (b.y - a.y) * wf;
        v1.z = a.z + (b.z - a.z) * wf; v1.w = a.w + (b.w - a.w) * wf;
    }
    {
        const int Ts = T_LEN / 4;
        float coord = (t + 0.5f) * 0.25f - 0.5f;
        coord = fminf(fmaxf(coord, 0.f), (float)(Ts - 1));
        int lo = (int)floorf(coord);
        int hi = min(lo + 1, Ts - 1);
        float wf = coord - (float)lo;
        float4 a = *(const float4*)&ys2[(size_t)(bb * Ts + lo) * DI + c4];
        float4 b = *(const float4*)&ys2[(size_t)(bb * Ts + hi) * DI + c4];
        v2.x = a.x + (b.x - a.x) * wf; v2.y = a.y + (b.y - a.y) * wf;
        v2.z = a.z + (b.z - a.z) * wf; v2.w = a.w + (b.w - a.w) * wf;
    }

    float w0 = g_sw[0], w1 = g_sw[1], w2 = g_sw[2];
    float4 f, cx;
    f.x = w0 * v0.x + w1 * v1.x + w2 * v2.x;
    f.y = w0 * v0.y + w1 * v1.y + w2 * v2.y;
    f.z = w0 * v0.z + w1 * v1.z + w2 * v2.z;
    f.w = w0 * v0.w + w1 * v1.w + w2 * v2.w;
    const float third = 1.f / 3.f;
    cx.x = (v0.x + v1.x + v2.x) * third;
    cx.y = (v0.y + v1.y + v2.y) * third;
    cx.z = (v0.z + v1.z + v2.z) * third;
    cx.w = (v0.w + v1.w + v2.w) * third;

    size_t o = (size_t)rt * DI + c4;
    *(float4*)&fused[o] = f;
    *(float4*)&ctx[o] = cx;
}

// ---------------- LayerNorm over last dim (1024), float4 ----------------
__global__ __launch_bounds__(256)
void ln_kernel(const float* __restrict__ y, const float* __restrict__ g,
               const float* __restrict__ b, float* __restrict__ out) {
    int row = blockIdx.x;
    const float* yr = y + (size_t)row * DIM;
    int c4 = threadIdx.x * 4;
    float4 v = *(const float4*)&yr[c4];
    float s  = v.x + v.y + v.z + v.w;
    float s2 = v.x * v.x + v.y * v.y + v.z * v.z + v.w * v.w;
#pragma unroll
    for (int o = 16; o > 0; o >>= 1) {
        s  += __shfl_down_sync(0xffffffffu, s, o);
        s2 += __shfl_down_sync(0xffffffffu, s2, o);
    }
    __shared__ float shs[8], shs2[8];
    __shared__ float smu, srstd;
    int wid = threadIdx.x >> 5, lane = threadIdx.x & 31;
    if (lane == 0) { shs[wid] = s; shs2[wid] = s2; }
    __syncthreads();
    if (wid == 0) {
        s  = lane < 8 ? shs[lane]  : 0.f;
        s2 = lane < 8 ? shs2[lane] : 0.f;
#pragma unroll
        for (int o = 4; o > 0; o >>= 1) {
            s  += __shfl_down_sync(0xffffffffu, s, o);
            s2 += __shfl_down_sync(0xffffffffu, s2, o);
        }
        if (lane == 0) {
            float mu = s / DIM;
            float var = s2 / DIM - mu * mu;
            smu = mu;
            srstd = rsqrtf(var + LN_EPS);
        }
    }
    __syncthreads();
    float mu = smu, rstd = srstd;
    float4 gv = *(const float4*)&g[c4];
    float4 bv = *(const float4*)&b[c4];
    float4 o;
    o.x = (v.x - mu) * rstd * gv.x + bv.x;
    o.y = (v.y - mu) * rstd * gv.y + bv.y;
    o.z = (v.z - mu) * rstd * gv.z + bv.z;
    o.w = (v.w - mu) * rstd * gv.w + bv.w;
    *(float4*)&out[(size_t)row * DIM + c4] = o;
}

// ---------------- launch ----------------
extern "C" void kernel_launch(void* const* d_in, const int* in_sizes, int n_in,
                              void* d_out, int out_size) {
    const float* x        = (const float*)d_in[0];
    const float* in_proj  = (const float*)d_in[1];
    const float* conv_w   = (const float*)d_in[2];
    const float* conv_b   = (const float*)d_in[3];
    const float* xproj_w  = (const float*)d_in[4];
    const float* dtproj_w = (const float*)d_in[5];
    const float* dtproj_b = (const float*)d_in[6];
    const float* D_param  = (const float*)d_in[7];
    const float* scale_w  = (const float*)d_in[8];
    const float* cg_w1    = (const float*)d_in[9];
    const float* cg_w2    = (const float*)d_in[10];
    const float* out_proj = (const float*)d_in[11];
    const float* ln_g     = (const float*)d_in[12];
    const float* ln_b     = (const float*)d_in[13];
    float* out = (float*)d_out;

    float *p_xz, *p_xs, *p_xc, *p_bssm, *p_ys0, *p_ys1, *p_ys2,
          *p_fused, *p_ctx, *p_h, *p_mmin, *p_preln;
    uint32_t* p_wh;
    cudaGetSymbolAddress((void**)&p_xz, g_xz);
    cudaGetSymbolAddress((void**)&p_xs, g_xs);
    cudaGetSymbolAddress((void**)&p_xc, g_xc);
    cudaGetSymbolAddress((void**)&p_bssm, g_bssm);
    cudaGetSymbolAddress((void**)&p_ys0, g_ys0);
    cudaGetSymbolAddress((void**)&p_ys1, g_ys1);
    cudaGetSymbolAddress((void**)&p_ys2, g_ys2);
    cudaGetSymbolAddress((void**)&p_fused, g_fused);
    cudaGetSymbolAddress((void**)&p_ctx, g_ctx);
    cudaGetSymbolAddress((void**)&p_h, g_h);
    cudaGetSymbolAddress((void**)&p_mmin, g_mmin);
    cudaGetSymbolAddress((void**)&p_preln, g_preln);
    cudaGetSymbolAddress((void**)&p_wh, g_wh);

    // half2 weight copies (k-paired)
    uint32_t* p_w0h = p_wh;                                   // [512][4096]
    uint32_t* p_w1h = p_w0h + (size_t)(DIM / 2) * 2 * DI;     // [1024][1024]
    uint32_t* p_w2h = p_w1h + (size_t)(DI / 2) * (DI / 2);    // [512][2048]
    uint32_t* p_w3h = p_w2h + (size_t)(DI / 4) * DI;          // [1024][1024]

    softmax3_kernel<<<1, 1>>>(scale_w);

    // 0) preconvert weights to half2 (k-paired) layout
    {
        int n;
        n = (DIM / 2) * 2 * DI;
        cvt_h2_kernel<<<(n + 255) / 256, 256>>>(in_proj, p_w0h, DIM / 2, 2 * DI);
        n = (DI / 2) * (DI / 2);
        cvt_h2_kernel<<<(n + 255) / 256, 256>>>(cg_w1, p_w1h, DI / 2, DI / 2);
        n = (DI / 4) * DI;
        cvt_h2_kernel<<<(n + 255) / 256, 256>>>(cg_w2, p_w2h, DI / 4, DI);
        n = (DI / 2) * DIM;
        cvt_h2_kernel<<<(n + 255) / 256, 256>>>(out_proj, p_w3h, DI / 2, DIM);
    }

    // 1) xz = x @ in_proj_w   (16384 x 4096, K=1024)
    {
        dim3 grid(2 * DI / 128, ROWS_FULL / 128);
        tgemm_kernel<0><<<grid, 256>>>(x, p_w0h, p_xz, ROWS_FULL, 2 * DI, DIM,
                                       nullptr, nullptr);
    }

    // 2) per-scale SSM path
    float* ys_bufs[NSCALES] = {p_ys0, p_ys1, p_ys2};
    for (int s = 0; s < NSCALES; s++) {
        int stride = 1 << s;
        int Ts = T_LEN / stride;
        int rows = BATCH * Ts;
        int total4 = rows * (DI / 4);
        const float* xin;
        int ld;
        if (s == 0) {
            xin = p_xz; ld = 2 * DI;
        } else {
            downsample_kernel<<<(total4 + 255) / 256, 256>>>(p_xz, p_xs, Ts, stride);
            xin = p_xs; ld = DI;
        }
        conv_silu_kernel<<<(total4 + 255) / 256, 256>>>(xin, ld,
                                                        conv_w + (size_t)s * DI * KCONV,
                                                        conv_b + (size_t)s * DI,
                                                        p_xc, Ts);
        {
            dim3 bgrid(rows / 64, NSPLIT);
            bssm_kernel<<<bgrid, 256>>>(p_xc, xproj_w + (size_t)s * DI * 2 * DSTATE,
                                        p_bssm, rows);
        }
        ssm_pw_kernel<<<rows, 256>>>(p_xc, p_bssm,
                                     dtproj_w + (size_t)s * DSTATE * DI,
                                     dtproj_b + (size_t)s * DI,
                                     D_param + (size_t)s * DI,
                                     xin, ld, ys_bufs[s], rows);
    }

    // 2b) merged upsample + fuse
    {
        int total4 = ROWS_FULL * (DI / 4);
        ups_fuse_kernel<<<(total4 + 255) / 256, 256>>>(p_ys0, p_ys1, p_ys2, p_fused, p_ctx);
    }

    // 3) h = silu(ctx @ cg_w1)   (16384 x 1024, K=2048)
    {
        dim3 grid((DI / 2) / 128, ROWS_FULL / 128);
        tgemm_kernel<1><<<grid, 256>>>(p_ctx, p_w1h, p_h, ROWS_FULL, DI / 2, DI,
                                       nullptr, nullptr);
    }
    // 4) mm_in = fused * sigmoid(h @ cg_w2) * silu(gate)  (16384 x 2048, K=1024)
    {
        dim3 grid(DI / 128, ROWS_FULL / 128);
        tgemm_kernel<2><<<grid, 256>>>(p_h, p_w2h, p_mmin, ROWS_FULL, DI, DI / 2,
                                       p_fused, p_xz + DI);
    }
    // 5) preln = mm_in @ out_proj + x   (16384 x 1024, K=2048)
    {
        dim3 grid(DIM / 128, ROWS_FULL / 128);
        tgemm_kernel<3><<<grid, 256>>>(p_mmin, p_w3h, p_preln, ROWS_FULL, DIM, DI,
                                       x, nullptr);
    }
    // 6) LayerNorm -> out
    ln_kernel<<<ROWS_FULL, 256>>>(p_preln, ln_g, ln_b, out);
}

// round 14
// speedup vs baseline: 2.3394x; 1.0191x over previous
#include <cuda_runtime.h>
#include <cuda_fp16.h>
#include <math.h>
#include <stdint.h>

// ---------------- problem constants ----------------
#define BATCH 4
#define T_LEN 4096
#define DIM 1024
#define DI 2048            // d_inner
#define DSTATE 16
#define KCONV 4
#define NSCALES 3
#define ROWS_FULL (BATCH * T_LEN)          // 16384
#define LN_EPS 1e-5f
#define NSPLIT 8           // bssm K-split factor

// ---------------- scratch (__device__ globals; no allocation allowed) ------
__device__ __align__(16) float g_xz[ROWS_FULL * 2 * DI];        // (x_in | gate)
__device__ __align__(16) float g_xs[ROWS_FULL * DI / 2];        // downsampled input
__device__ __align__(16) float g_xc[ROWS_FULL * DI];            // conv+silu output
__device__ __align__(16) float g_bssm[NSPLIT * ROWS_FULL * DSTATE];  // K-split partials
__device__ __align__(16) float g_ys0[ROWS_FULL * DI];
__device__ __align__(16) float g_ys1[(ROWS_FULL / 2) * DI];
__device__ __align__(16) float g_ys2[(ROWS_FULL / 4) * DI];
__device__ __align__(16) float g_fused[ROWS_FULL * DI];
__device__ __align__(16) float g_ctx[ROWS_FULL * DI];
__device__ __align__(16) float g_h[ROWS_FULL * (DI / 2)];
__device__ __align__(16) float g_mmin[ROWS_FULL * DI];
__device__ __align__(16) float g_preln[ROWS_FULL * DIM];
// half2 (k-paired) weight copies: in_proj | cg_w1 | cg_w2 | out_proj
__device__ __align__(16) uint32_t g_wh[5242880];
__device__ float g_sw[NSCALES];

// ---------------- helpers ----------------
__device__ __forceinline__ float sigmoidf(float x) { return 1.f / (1.f + expf(-x)); }
__device__ __forceinline__ float siluf(float x)    { return x / (1.f + expf(-x)); }
__device__ __forceinline__ float softplusf(float x){ return x > 20.f ? x : log1pf(expf(x)); }

__device__ __forceinline__ uint32_t pack_h2(float lo, float hi) {
    __half2 h = __floats2half2_rn(lo, hi);
    return *(uint32_t*)&h;
}

__device__ __forceinline__ void mma_f16(float* c, const uint32_t* a, uint32_t b0, uint32_t b1) {
    asm volatile(
        "mma.sync.aligned.m16n8k16.row.col.f32.f16.f16.f32 "
        "{%0,%1,%2,%3}, {%4,%5,%6,%7}, {%8,%9}, {%0,%1,%2,%3};\n"
        : "+f"(c[0]), "+f"(c[1]), "+f"(c[2]), "+f"(c[3])
        : "r"(a[0]), "r"(a[1]), "r"(a[2]), "r"(a[3]), "r"(b0), "r"(b1));
}

// ---------------- softmax over 3 scale weights ----------------
__global__ void softmax3_kernel(const float* __restrict__ sw) {
    float a = sw[0], b = sw[1], c = sw[2];
    float m = fmaxf(a, fmaxf(b, c));
    float ea = expf(a - m), eb = expf(b - m), ec = expf(c - m);
    float inv = 1.f / (ea + eb + ec);
    g_sw[0] = ea * inv; g_sw[1] = eb * inv; g_sw[2] = ec * inv;
}

// ---------------- weight preconvert: W[K][N] f32 -> Wh2[K/2][N] half2 -------
__global__ void cvt_h2_kernel(const float* __restrict__ in, uint32_t* __restrict__ out,
                              int Kh, int N) {
    int i = blockIdx.x * blockDim.x + threadIdx.x;
    int total = Kh * N;
    if (i >= total) return;
    int p = i / N, n = i - p * N;
    float a = in[(size_t)(2 * p) * N + n];
    float b = in[(size_t)(2 * p + 1) * N + n];
    out[(size_t)p * N + n] = pack_h2(a, b);
}

// ---------------- FP16 tensor-core GEMM with fused epilogues (R13 winner) ---
#define A_GRP 132   // u32 stride per (mi,kstep) fragment group (128 + 4 pad)
#define B_GRP 130   // u32 stride per ni group (2*64 + 2 pad)

template<int EPI>
__global__ __launch_bounds__(256)
void tgemm_kernel(const float* __restrict__ A, const uint32_t* __restrict__ Bh,
                  float* __restrict__ C, int M, int N, int K,
                  const float* __restrict__ e1, const float* __restrict__ e2) {
    __shared__ __align__(16) uint32_t Asm[16 * A_GRP];
    __shared__ __align__(16) uint32_t Bsm[16 * B_GRP];

    const int tid  = threadIdx.x;
    const int warp = tid >> 5;
    const int lane = tid & 31;
    const int wm = warp >> 2;
    const int wn = warp & 3;
    const int g  = lane >> 2;
    const int tg = lane & 3;

    const int m0 = blockIdx.y * 128;
    const int n0 = blockIdx.x * 128;

    float acc[4][4][4];
#pragma unroll
    for (int i = 0; i < 4; i++)
#pragma unroll
        for (int j = 0; j < 4; j++)
#pragma unroll
            for (int q = 0; q < 4; q++) acc[i][j][q] = 0.f;

    float4 a_pre[4];
    uint4  b_pre[2];

#pragma unroll
    for (int it = 0; it < 4; it++) {
        int v = tid + it * 256;
        int r = v >> 3, c4 = (v & 7) * 4;
        a_pre[it] = *(const float4*)&A[(size_t)(m0 + r) * K + c4];
    }
#pragma unroll
    for (int it = 0; it < 2; it++) {
        int v = tid + it * 256;
        int prow = v >> 5, n4 = (v & 31) * 4;
        b_pre[it] = *(const uint4*)&Bh[(size_t)prow * N + n0 + n4];
    }

    for (int k0 = 0; k0 < K; k0 += 32) {
#pragma unroll
        for (int it = 0; it < 4; it++) {
            int v = tid + it * 256;
            int r = v >> 3, c4 = (v & 7) * 4;
            int mi = r >> 4, rr = r & 15;
            float va[4] = {a_pre[it].x, a_pre[it].y, a_pre[it].z, a_pre[it].w};
#pragma unroll
            for (int j = 0; j < 2; j++) {
                int c = c4 + 2 * j;
                int p = (c & 15) >> 1, kstep = c >> 4;
                int ls = (rr & 7) * 4 + (p & 3);
                int slot = (p >> 2) * 2 + (rr >> 3);
                Asm[(mi * 2 + kstep) * A_GRP + ls * 4 + slot] = pack_h2(va[2 * j], va[2 * j + 1]);
            }
        }
#pragma unroll
        for (int it = 0; it < 2; it++) {
            int v = tid + it * 256;
            int prow = v >> 5, n4 = (v & 31) * 4;
            int pp = prow & 7, kstep = prow >> 3;
            uint32_t vb[4] = {b_pre[it].x, b_pre[it].y, b_pre[it].z, b_pre[it].w};
#pragma unroll
            for (int j = 0; j < 4; j++) {
                int nn = n4 + j;
                int ni = nn >> 3, cc = nn & 7;
                int ls = cc * 4 + (pp & 3);
                int slot = pp >> 2;
                Bsm[ni * B_GRP + kstep * 64 + ls * 2 + slot] = vb[j];
            }
        }
        __syncthreads();

        if (k0 + 32 < K) {
#pragma unroll
            for (int it = 0; it < 4; it++) {
                int v = tid + it * 256;
                int r = v >> 3, c4 = (v & 7) * 4;
                a_pre[it] = *(const float4*)&A[(size_t)(m0 + r) * K + (k0 + 32) + c4];
            }
            int ph0 = (k0 + 32) >> 1;
#pragma unroll
            for (int it = 0; it < 2; it++) {
                int v = tid + it * 256;
                int prow = v >> 5, n4 = (v & 31) * 4;
                b_pre[it] = *(const uint4*)&Bh[(size_t)(ph0 + prow) * N + n0 + n4];
            }
        }

#pragma unroll
        for (int kstep = 0; kstep < 2; kstep++) {
            uint32_t bq[4][2];
#pragma unroll
            for (int nj = 0; nj < 4; nj++) {
                int ni_g = wn * 4 + nj;
                *(uint2*)bq[nj] = *(const uint2*)&Bsm[ni_g * B_GRP + kstep * 64 + lane * 2];
            }
            uint32_t af[4][4];
#pragma unroll
            for (int mi = 0; mi < 4; mi++) {
                int mi_g = wm * 4 + mi;
                *(uint4*)af[mi] = *(const uint4*)&Asm[(mi_g * 2 + kstep) * A_GRP + lane * 4];
            }
#pragma unroll
            for (int mi = 0; mi < 4; mi++)
#pragma unroll
                for (int nj = 0; nj < 4; nj++)
                    mma_f16(acc[mi][nj], af[mi], bq[nj][0], bq[nj][1]);
        }
        __syncthreads();
    }

#pragma unroll
    for (int mi = 0; mi < 4; mi++) {
#pragma unroll
        for (int ni = 0; ni < 4; ni++) {
            int r0 = m0 + wm * 64 + mi * 16 + g;
            int cb = n0 + wn * 32 + ni * 8 + tg * 2;
#pragma unroll
            for (int half = 0; half < 2; half++) {
                int row = r0 + half * 8;
                float v0 = acc[mi][ni][half * 2 + 0];
                float v1 = acc[mi][ni][half * 2 + 1];
                size_t idx = (size_t)row * N + cb;
                float o0, o1;
                if (EPI == 0) {
                    o0 = v0; o1 = v1;
                } else if (EPI == 1) {
                    o0 = siluf(v0); o1 = siluf(v1);
                } else if (EPI == 2) {
                    float g0 = e2[(size_t)row * (2 * DI) + cb];
                    float g1 = e2[(size_t)row * (2 * DI) + cb + 1];
                    o0 = e1[idx] * sigmoidf(v0) * siluf(g0);
                    o1 = e1[idx + 1] * sigmoidf(v1) * siluf(g1);
                } else {
                    o0 = v0 + e1[idx];
                    o1 = v1 + e1[idx + 1];
                }
                *(float2*)&C[idx] = make_float2(o0, o1);
            }
        }
    }
}

// ---------------- downsample (mean pool over time), float4 ----------------
__global__ void downsample_kernel(const float* __restrict__ xz, float* __restrict__ xs,
                                  int Ts, int stride) {
    int idx = blockIdx.x * blockDim.x + threadIdx.x;
    int total = BATCH * Ts * (DI / 4);
    if (idx >= total) return;
    int c4 = (idx & (DI / 4 - 1)) * 4;
    int rt = idx / (DI / 4);
    int t = rt % Ts;
    int bb = rt / Ts;
    float4 acc = make_float4(0.f, 0.f, 0.f, 0.f);
    for (int r = 0; r < stride; r++) {
        float4 v = *(const float4*)&xz[(size_t)(bb * T_LEN + t * stride + r) * (2 * DI) + c4];
        acc.x += v.x; acc.y += v.y; acc.z += v.z; acc.w += v.w;
    }
    float inv = 1.f / (float)stride;
    acc.x *= inv; acc.y *= inv; acc.z *= inv; acc.w *= inv;
    *(float4*)&xs[(size_t)(bb * Ts + t) * DI + c4] = acc;
}

// ---------------- causal depthwise conv (K=4) + silu, float4 ----------------
__global__ void conv_silu_kernel(const float* __restrict__ x, int ld,
                                 const float* __restrict__ w, const float* __restrict__ b,
                                 float* __restrict__ xc, int Ts) {
    int idx = blockIdx.x * blockDim.x + threadIdx.x;
    int total = BATCH * Ts * (DI / 4);
    if (idx >= total) return;
    int c4 = (idx & (DI / 4 - 1)) * 4;
    int rt = idx / (DI / 4);
    int t = rt % Ts;
    int bb = rt / Ts;
    float4 w0 = *(const float4*)&w[(c4 + 0) * KCONV];
    float4 w1 = *(const float4*)&w[(c4 + 1) * KCONV];
    float4 w2 = *(const float4*)&w[(c4 + 2) * KCONV];
    float4 w3 = *(const float4*)&w[(c4 + 3) * KCONV];
    float4 acc = *(const float4*)&b[c4];
    const float wk[4][4] = {{w0.x, w0.y, w0.z, w0.w}, {w1.x, w1.y, w1.z, w1.w},
                            {w2.x, w2.y, w2.z, w2.w}, {w3.x, w3.y, w3.z, w3.w}};
#pragma unroll
    for (int k = 0; k < KCONV; k++) {
        int tt = t - (KCONV - 1) + k;
        if (tt >= 0) {
            float4 v = *(const float4*)&x[(size_t)(bb * Ts + tt) * ld + c4];
            acc.x = fmaf(wk[0][k], v.x, acc.x);
            acc.y = fmaf(wk[1][k], v.y, acc.y);
            acc.z = fmaf(wk[2][k], v.z, acc.z);
            acc.w = fmaf(wk[3][k], v.w, acc.w);
        }
    }
    acc.x = siluf(acc.x); acc.y = siluf(acc.y);
    acc.z = siluf(acc.z); acc.w = siluf(acc.w);
    *(float4*)&xc[(size_t)rt * DI + c4] = acc;
}

// ---------------- B_ssm partials, register-tiled 4x4, transposed smem -------
// grid = (rows/256, NSPLIT). Block 256: thread (rg 0..63, jq 0..3) computes
// rows rg*4..rg*4+3, cols jq*4..jq*4+3. K chunk of 32 staged transposed.
#define BSSM_ROWS 256
#define XT_P 257

__global__ __launch_bounds__(256)
void bssm_kernel(const float* __restrict__ xc, const float* __restrict__ xproj,
                 float* __restrict__ bssm_p, int rows) {
    __shared__ float xt[32 * XT_P];                 // [kk][row], pad 257
    __shared__ __align__(16) float ws[32 * 16];     // [kk][j]
    const int tid = threadIdx.x;
    const int row0 = blockIdx.x * BSSM_ROWS;
    const int ks0 = blockIdx.y * (DI / NSPLIT);     // 256-wide K chunk
    const int rg = tid >> 2;                        // 0..63
    const int jq = tid & 3;                         // 0..3
    float acc[4][4];
#pragma unroll
    for (int i = 0; i < 4; i++)
#pragma unroll
        for (int j = 0; j < 4; j++) acc[i][j] = 0.f;

    for (int k0 = ks0; k0 < ks0 + DI / NSPLIT; k0 += 32) {
        // load x tile transposed: 256 rows x 32 kk
#pragma unroll
        for (int i = 0; i < 8; i++) {
            int v = tid + i * 256;
            int lr = v >> 3, c4 = (v & 7) * 4;
            float4 xv = *(const float4*)&xc[(size_t)(row0 + lr) * DI + k0 + c4];
            xt[(c4 + 0) * XT_P + lr] = xv.x;
            xt[(c4 + 1) * XT_P + lr] = xv.y;
            xt[(c4 + 2) * XT_P + lr] = xv.z;
            xt[(c4 + 3) * XT_P + lr] = xv.w;
        }
        // load w tile: 32 kk x 16 j
        {
            int kk = tid >> 4, j = tid & 15;
#pragma unroll
            for (int i = 0; i < 2; i++)
                ws[(kk + i * 16) * 16 + j] = xproj[(size_t)(k0 + kk + i * 16) * (2 * DSTATE) + j];
        }
        __syncthreads();
#pragma unroll 8
        for (int kk = 0; kk < 32; kk++) {
            float4 w4 = *(const float4*)&ws[kk * 16 + jq * 4];
            float x0 = xt[kk * XT_P + rg * 4 + 0];
            float x1 = xt[kk * XT_P + rg * 4 + 1];
            float x2 = xt[kk * XT_P + rg * 4 + 2];
            float x3 = xt[kk * XT_P + rg * 4 + 3];
            acc[0][0] = fmaf(x0, w4.x, acc[0][0]); acc[0][1] = fmaf(x0, w4.y, acc[0][1]);
            acc[0][2] = fmaf(x0, w4.z, acc[0][2]); acc[0][3] = fmaf(x0, w4.w, acc[0][3]);
            acc[1][0] = fmaf(x1, w4.x, acc[1][0]); acc[1][1] = fmaf(x1, w4.y, acc[1][1]);
            acc[1][2] = fmaf(x1, w4.z, acc[1][2]); acc[1][3] = fmaf(x1, w4.w, acc[1][3]);
            acc[2][0] = fmaf(x2, w4.x, acc[2][0]); acc[2][1] = fmaf(x2, w4.y, acc[2][1]);
            acc[2][2] = fmaf(x2, w4.z, acc[2][2]); acc[2][3] = fmaf(x2, w4.w, acc[2][3]);
            acc[3][0] = fmaf(x3, w4.x, acc[3][0]); acc[3][1] = fmaf(x3, w4.y, acc[3][1]);
            acc[3][2] = fmaf(x3, w4.z, acc[3][2]); acc[3][3] = fmaf(x3, w4.w, acc[3][3]);
        }
        __syncthreads();
    }
#pragma unroll
    for (int i = 0; i < 4; i++) {
        size_t o = ((size_t)blockIdx.y * rows + row0 + rg * 4 + i) * DSTATE + jq * 4;
        *(float4*)&bssm_p[o] = *(float4*)acc[i];
    }
}

// ---------------- SSM pointwise: 8 rows/block, dtw slice in registers -------
// grid = (rows/8, DI/1024). Block 256: thread owns cols c4..c4+3, loops 8 rows.
__global__ __launch_bounds__(256)
void ssm_pw_kernel(const float* __restrict__ xc, const float* __restrict__ bssm_p,
                   const float* __restrict__ dtw, const float* __restrict__ dtb,
                   const float* __restrict__ D, const float* __restrict__ xs, int ld,
                   float* __restrict__ ys, int rows) {
    const int r0 = blockIdx.x * 8;
    const int c4 = blockIdx.y * 1024 + threadIdx.x * 4;

    float4 wv[DSTATE];
#pragma unroll
    for (int k = 0; k < DSTATE; k++)
        wv[k] = *(const float4*)&dtw[k * DI + c4];
    float4 dtb4 = *(const float4*)&dtb[c4];
    float4 D4   = *(const float4*)&D[c4];

    __shared__ float bs[8 * DSTATE];
    if (threadIdx.x < 8 * DSTATE) {
        int rr = threadIdx.x >> 4, k = threadIdx.x & 15;
        float v = 0.f;
#pragma unroll
        for (int sp = 0; sp < NSPLIT; sp++)
            v += bssm_p[((size_t)sp * rows + r0 + rr) * DSTATE + k];
        bs[rr * DSTATE + k] = v;
    }
    __syncthreads();

#pragma unroll
    for (int rr = 0; rr < 8; rr++) {
        int row = r0 + rr;
        float4 dt = dtb4;
#pragma unroll
        for (int k = 0; k < DSTATE; k++) {
            float bk = bs[rr * DSTATE + k];
            dt.x = fmaf(bk, wv[k].x, dt.x);
            dt.y = fmaf(bk, wv[k].y, dt.y);
            dt.z = fmaf(bk, wv[k].z, dt.z);
            dt.w = fmaf(bk, wv[k].w, dt.w);
        }
        float4 xcv = *(const float4*)&xc[(size_t)row * DI + c4];
        float4 xv  = *(const float4*)&xs[(size_t)row * ld + c4];
        float4 o;
        o.x = xcv.x * sigmoidf(softplusf(dt.x)) + D4.x * xv.x;
        o.y = xcv.y * sigmoidf(softplusf(dt.y)) + D4.y * xv.y;
        o.z = xcv.z * sigmoidf(softplusf(dt.z)) + D4.z * xv.z;
        o.w = xcv.w * sigmoidf(softplusf(dt.w)) + D4.w * xv.w;
        *(float4*)&ys[(size_t)row * DI + c4] = o;
    }
}

// ---------------- merged upsample + fuse (all 3 scales in one pass) ----------
__global__ void ups_fuse_kernel(const float* __restrict__ ys0,
                                const float* __restrict__ ys1,
                                const float* __restrict__ ys2,
                                float* __restrict__ fused, float* __restrict__ ctx) {
    int idx = blockIdx.x * blockDim.x + threadIdx.x;
    const int total4 = ROWS_FULL * (DI / 4);
    if (idx >= total4) return;
    int c4 = (idx & (DI / 4 - 1)) * 4;
    int rt = idx / (DI / 4);
    int t = rt % T_LEN;
    int bb = rt / T_LEN;

    float4 v0 = *(const float4*)&ys0[(size_t)(bb * T_LEN + t) * DI + c4];

    float4 v1, v2;
    {
        const int Ts = T_LEN / 2;
        float coord = (t + 0.5f) * 0.5f - 0.5f;
        coord = fminf(fmaxf(coord, 0.f), (float)(Ts - 1));
        int lo = (int)floorf(coord);
        int hi = min(lo + 1, Ts - 1);
        float wf = coord - (float)lo;
        float4 a = *(const float4*)&ys1[(size_t)(bb * Ts + lo) * DI + c4];
        float4 b = *(const float4*)&ys1[(size_t)(bb * Ts + hi) * DI + c4];
        v1.x = a.x + (b.x - a.x) * wf; v1.y = a.y + (b.y - a.y) * wf;
        v1.z = a.z + (b.z - a.z) * wf; v1.w = a.w + (b.w - a.w) * wf;
    }
    {
        const int Ts = T_LEN / 4;
        float coord = (t + 0.5f) * 0.25f - 0.5f;
        coord = fminf(fmaxf(coord, 0.f), (float)(Ts - 1));
        int lo = (int)floorf(coord);
        int hi = min(lo + 1, Ts - 1);
        float wf = coord - (float)lo;
        float4 a = *(const float4*)&ys2[(size_t)(bb * Ts + lo) * DI + c4];
        float4 b = *(const float4*)&ys2[(size_t)(bb * Ts + hi) * DI + c4];
        v2.x = a.x + (b.x - a.x) * wf; v2.y = a.y + (b.y - a.y) * wf;
        v2.z = a.z + (b.z - a.z) * wf; v2.w = a.w + (b.w - a.w) * wf;
    }

    float w0 = g_sw[0], w1 = g_sw[1], w2 = g_sw[2];
    float4 f, cx;
    f.x = w0 * v0.x + w1 * v1.x + w2 * v2.x;
    f.y = w0 * v0.y + w1 * v1.y + w2 * v2.y;
    f.z = w0 * v0.z + w1 * v1.z + w2 * v2.z;
    f.w = w0 * v0.w + w1 * v1.w + w2 * v2.w;
    const float third = 1.f / 3.f;
    cx.x = (v0.x + v1.x + v2.x) * third;
    cx.y = (v0.y + v1.y + v2.y) * third;
    cx.z = (v0.z + v1.z + v2.z) * third;
    cx.w = (v0.w + v1.w + v2.w) * third;

    size_t o = (size_t)rt * DI + c4;
    *(float4*)&fused[o] = f;
    *(float4*)&ctx[o] = cx;
}

// ---------------- LayerNorm over last dim (1024), float4 ----------------
__global__ __launch_bounds__(256)
void ln_kernel(const float* __restrict__ y, const float* __restrict__ g,
               const float* __restrict__ b, float* __restrict__ out) {
    int row = blockIdx.x;
    const float* yr = y + (size_t)row * DIM;
    int c4 = threadIdx.x * 4;
    float4 v = *(const float4*)&yr[c4];
    float s  = v.x + v.y + v.z + v.w;
    float s2 = v.x * v.x + v.y * v.y + v.z * v.z + v.w * v.w;
#pragma unroll
    for (int o = 16; o > 0; o >>= 1) {
        s  += __shfl_down_sync(0xffffffffu, s, o);
        s2 += __shfl_down_sync(0xffffffffu, s2, o);
    }
    __shared__ float shs[8], shs2[8];
    __shared__ float smu, srstd;
    int wid = threadIdx.x >> 5, lane = threadIdx.x & 31;
    if (lane == 0) { shs[wid] = s; shs2[wid] = s2; }
    __syncthreads();
    if (wid == 0) {
        s  = lane < 8 ? shs[lane]  : 0.f;
        s2 = lane < 8 ? shs2[lane] : 0.f;
#pragma unroll
        for (int o = 4; o > 0; o >>= 1) {
            s  += __shfl_down_sync(0xffffffffu, s, o);
            s2 += __shfl_down_sync(0xffffffffu, s2, o);
        }
        if (lane == 0) {
            float mu = s / DIM;
            float var = s2 / DIM - mu * mu;
            smu = mu;
            srstd = rsqrtf(var + LN_EPS);
        }
    }
    __syncthreads();
    float mu = smu, rstd = srstd;
    float4 gv = *(const float4*)&g[c4];
    float4 bv = *(const float4*)&b[c4];
    float4 o;
    o.x = (v.x - mu) * rstd * gv.x + bv.x;
    o.y = (v.y - mu) * rstd * gv.y + bv.y;
    o.z = (v.z - mu) * rstd * gv.z + bv.z;
    o.w = (v.w - mu) * rstd * gv.w + bv.w;
    *(float4*)&out[(size_t)row * DIM + c4] = o;
}

// ---------------- launch ----------------
extern "C" void kernel_launch(void* const* d_in, const int* in_sizes, int n_in,
                              void* d_out, int out_size) {
    const float* x        = (const float*)d_in[0];
    const float* in_proj  = (const float*)d_in[1];
    const float* conv_w   = (const float*)d_in[2];
    const float* conv_b   = (const float*)d_in[3];
    const float* xproj_w  = (const float*)d_in[4];
    const float* dtproj_w = (const float*)d_in[5];
    const float* dtproj_b = (const float*)d_in[6];
    const float* D_param  = (const float*)d_in[7];
    const float* scale_w  = (const float*)d_in[8];
    const float* cg_w1    = (const float*)d_in[9];
    const float* cg_w2    = (const float*)d_in[10];
    const float* out_proj = (const float*)d_in[11];
    const float* ln_g     = (const float*)d_in[12];
    const float* ln_b     = (const float*)d_in[13];
    float* out = (float*)d_out;

    float *p_xz, *p_xs, *p_xc, *p_bssm, *p_ys0, *p_ys1, *p_ys2,
          *p_fused, *p_ctx, *p_h, *p_mmin, *p_preln;
    uint32_t* p_wh;
    cudaGetSymbolAddress((void**)&p_xz, g_xz);
    cudaGetSymbolAddress((void**)&p_xs, g_xs);
    cudaGetSymbolAddress((void**)&p_xc, g_xc);
    cudaGetSymbolAddress((void**)&p_bssm, g_bssm);
    cudaGetSymbolAddress((void**)&p_ys0, g_ys0);
    cudaGetSymbolAddress((void**)&p_ys1, g_ys1);
    cudaGetSymbolAddress((void**)&p_ys2, g_ys2);
    cudaGetSymbolAddress((void**)&p_fused, g_fused);
    cudaGetSymbolAddress((void**)&p_ctx, g_ctx);
    cudaGetSymbolAddress((void**)&p_h, g_h);
    cudaGetSymbolAddress((void**)&p_mmin, g_mmin);
    cudaGetSymbolAddress((void**)&p_preln, g_preln);
    cudaGetSymbolAddress((void**)&p_wh, g_wh);

    uint32_t* p_w0h = p_wh;                                   // [512][4096]
    uint32_t* p_w1h = p_w0h + (size_t)(DIM / 2) * 2 * DI;     // [1024][1024]
    uint32_t* p_w2h = p_w1h + (size_t)(DI / 2) * (DI / 2);    // [512][2048]
    uint32_t* p_w3h = p_w2h + (size_t)(DI / 4) * DI;          // [1024][1024]

    softmax3_kernel<<<1, 1>>>(scale_w);

    // 0) preconvert weights to half2 (k-paired) layout
    {
        int n;
        n = (DIM / 2) * 2 * DI;
        cvt_h2_kernel<<<(n + 255) / 256, 256>>>(in_proj, p_w0h, DIM / 2, 2 * DI);
        n = (DI / 2) * (DI / 2);
        cvt_h2_kernel<<<(n + 255) / 256, 256>>>(cg_w1, p_w1h, DI / 2, DI / 2);
        n = (DI / 4) * DI;
        cvt_h2_kernel<<<(n + 255) / 256, 256>>>(cg_w2, p_w2h, DI / 4, DI);
        n = (DI / 2) * DIM;
        cvt_h2_kernel<<<(n + 255) / 256, 256>>>(out_proj, p_w3h, DI / 2, DIM);
    }

    // 1) xz = x @ in_proj_w   (16384 x 4096, K=1024)
    {
        dim3 grid(2 * DI / 128, ROWS_FULL / 128);
        tgemm_kernel<0><<<grid, 256>>>(x, p_w0h, p_xz, ROWS_FULL, 2 * DI, DIM,
                                       nullptr, nullptr);
    }

    // 2) per-scale SSM path
    float* ys_bufs[NSCALES] = {p_ys0, p_ys1, p_ys2};
    for (int s = 0; s < NSCALES; s++) {
        int stride = 1 << s;
        int Ts = T_LEN / stride;
        int rows = BATCH * Ts;
        int total4 = rows * (DI / 4);
        const float* xin;
        int ld;
        if (s == 0) {
            xin = p_xz; ld = 2 * DI;
        } else {
            downsample_kernel<<<(total4 + 255) / 256, 256>>>(p_xz, p_xs, Ts, stride);
            xin = p_xs; ld = DI;
        }
        conv_silu_kernel<<<(total4 + 255) / 256, 256>>>(xin, ld,
                                                        conv_w + (size_t)s * DI * KCONV,
                                                        conv_b + (size_t)s * DI,
                                                        p_xc, Ts);
        {
            dim3 bgrid(rows / BSSM_ROWS, NSPLIT);
            bssm_kernel<<<bgrid, 256>>>(p_xc, xproj_w + (size_t)s * DI * 2 * DSTATE,
                                        p_bssm, rows);
        }
        {
            dim3 sgrid(rows / 8, DI / 1024);
            ssm_pw_kernel<<<sgrid, 256>>>(p_xc, p_bssm,
                                          dtproj_w + (size_t)s * DSTATE * DI,
                                          dtproj_b + (size_t)s * DI,
                                          D_param + (size_t)s * DI,
                                          xin, ld, ys_bufs[s], rows);
        }
    }

    // 2b) merged upsample + fuse
    {
        int total4 = ROWS_FULL * (DI / 4);
        ups_fuse_kernel<<<(total4 + 255) / 256, 256>>>(p_ys0, p_ys1, p_ys2, p_fused, p_ctx);
    }

    // 3) h = silu(ctx @ cg_w1)   (16384 x 1024, K=2048)
    {
        dim3 grid((DI / 2) / 128, ROWS_FULL / 128);
        tgemm_kernel<1><<<grid, 256>>>(p_ctx, p_w1h, p_h, ROWS_FULL, DI / 2, DI,
                                       nullptr, nullptr);
    }
    // 4) mm_in = fused * sigmoid(h @ cg_w2) * silu(gate)  (16384 x 2048, K=1024)
    {
        dim3 grid(DI / 128, ROWS_FULL / 128);
        tgemm_kernel<2><<<grid, 256>>>(p_h, p_w2h, p_mmin, ROWS_FULL, DI, DI / 2,
                                       p_fused, p_xz + DI);
    }
    // 5) preln = mm_in @ out_proj + x   (16384 x 1024, K=2048)
    {
        dim3 grid(DIM / 128, ROWS_FULL / 128);
        tgemm_kernel<3><<<grid, 256>>>(p_mmin, p_w3h, p_preln, ROWS_FULL, DIM, DI,
                                       x, nullptr);
    }
    // 6) LayerNorm -> out
    ln_kernel<<<ROWS_FULL, 256>>>(p_preln, ln_g, ln_b, out);
}